// round 14
// baseline (speedup 1.0000x reference)
#include <cuda_runtime.h>
#include <math.h>
#include <stdint.h>

// ---------------- problem constants ----------------
#define NB   64
#define LL   2048
#define MS   12
#define DD   128
#define PP   16
#define SSTR 8
#define TT   256
#define KC   5
#define DR   32
#define NMB  2
#define DI   256
#define DCV  4
#define DSN  16
#define RKD  8
#define CC   18
#define BMR  768     // NB*MS
#define BT   16384   // NB*TT

#define PADK 68      // 64 + 4 pad (k-chunk tiles)
#define PADC 132     // 128 + 4 pad (C tile / staging rows)

// ---------------- scratch (device globals, no allocs) ----------------
__device__ float g_uA [BMR*DD*TT];
__device__ float g_uB [BMR*DD*TT];
__device__ float g_wA [BMR*DD*TT];
__device__ float g_wB [BMR*DD*TT];
__device__ float g_s2a[BMR*2*DD];
__device__ float g_s2b[BMR*2*DD];
__device__ float g_a  [BMR*DD];
__device__ float g_x2 [BT*DD];
__device__ float g_xz [BT*2*DI];
__device__ float g_xc [BT*DI];
__device__ float g_dbl[BT*40];
__device__ float g_dt [BT*DI];
__device__ float g_y  [BT*DI];
__device__ float g_out[BT*DD];

// ---------------- helpers ----------------
__device__ __forceinline__ float rne_tf32(float x) {
    uint32_t u = __float_as_uint(x);
    u += 0xFFFu + ((u >> 13) & 1u);
    u &= 0xFFFFE000u;
    return __uint_as_float(u);
}

__device__ __forceinline__ void mma_tf32(float c[4],
    uint32_t a0, uint32_t a1, uint32_t a2, uint32_t a3,
    uint32_t b0, uint32_t b1)
{
    asm volatile(
        "mma.sync.aligned.m16n8k8.row.col.f32.tf32.tf32.f32 "
        "{%0,%1,%2,%3}, {%4,%5,%6,%7}, {%8,%9}, {%0,%1,%2,%3};"
        : "+f"(c[0]), "+f"(c[1]), "+f"(c[2]), "+f"(c[3])
        : "r"(a0), "r"(a1), "r"(a2), "r"(a3), "r"(b0), "r"(b1));
}

// dyn smem: sB[128][PADK] + sA[128][PADK] + su[64][PADC]
#define SMEM_BLOCK ((2*128*PADK + 64*PADC) * 4)   // 103424 B
#define SMEM_GEMM  (2 * 128 * PADK * 4)           // 69632 B

// ---------------- stage 1: embedding conv (register-held inputs) ----------------
__global__ void k_emb(const float* __restrict__ xin,
                      const float* __restrict__ w,
                      const float* __restrict__ bias) {
    __shared__ float srow[LL];
    __shared__ float sw[DD*PP];
    __shared__ float sb[DD];
    int bm = blockIdx.x;
    int b = bm / MS, m = bm % MS;
    const float* xp = xin + (size_t)b * (LL*MS) + m;
    for (int l = threadIdx.x; l < LL; l += blockDim.x) srow[l] = xp[(size_t)l * MS];
    for (int i = threadIdx.x; i < DD*PP; i += blockDim.x) sw[i] = w[i];
    for (int i = threadIdx.x; i < DD; i += blockDim.x) sb[i] = bias[i];
    __syncthreads();
    int t = threadIdx.x;
    int base = t * SSTR - 4;
    float x[PP];
    #pragma unroll
    for (int p = 0; p < PP; p++) {
        int l = base + p;
        x[p] = (l >= 0 && l < LL) ? srow[l] : 0.0f;
    }
    float* outp = g_uA + (size_t)bm * (DD*TT);
    for (int d = 0; d < DD; d++) {
        float acc = sb[d];
        #pragma unroll
        for (int p = 0; p < PP; p++) acc += sw[d*PP + p] * x[p];
        outp[d*TT + t] = acc;
    }
}

// ---------------- fused block kernel: in-CTA SE + float4 staging + tf32 mma ----------------
// C[t][e] = sum_d V[t][d] * W[e][d];  V = gelu(dwconv(u [+ w_prev*a]))
// a computed in-CTA from s_in (previous layer t-sums) using previous layer SE weights.
__global__ void __launch_bounds__(256, 2) k_block_mma(
    const float* __restrict__ u_in, const float* __restrict__ w_prev,
    const float* __restrict__ s_in, float* __restrict__ u_out,
    float* __restrict__ w_out, float* __restrict__ s_out,
    const float* __restrict__ dww, const float* __restrict__ dwb,
    const float* __restrict__ pwA, const float* __restrict__ pwb,
    const float* __restrict__ sw1, const float* __restrict__ sb1,
    const float* __restrict__ sw2, const float* __restrict__ sb2,
    int apply)
{
    extern __shared__ float dsm[];
    float* sB = dsm;                 // weights [e=128][64] pad PADK
    float* sA = dsm + 128*PADK;      // v       [t=128][64] pad PADK
    float* su = dsm + 2*128*PADK;    // u stage [64 d-rows][PADC]
    float* sC = dsm;                 // reuse sB+sA: [e=128][t] pad PADC
    __shared__ float sdw[DD*KC];
    __shared__ float sdb[DD];
    __shared__ float sa[DD];
    __shared__ float sss[DD];
    __shared__ float shh[DR];

    int bm = blockIdx.y, bn = blockIdx.x, t0 = bn * 128;
    int tid = threadIdx.x;
    int warp = tid >> 5, lane = tid & 31;
    int mbase = (warp & 3) * 32, nbase = (warp >> 2) * 64;
    int qr = lane >> 2, kb = lane & 3;

    for (int i = tid; i < DD*KC; i += 256) sdw[i] = dww[i];
    for (int i = tid; i < DD; i += 256) sdb[i] = dwb[i];

    // ---- in-CTA SE: a = sigmoid(w2 @ relu(w1 @ mean_t(w_prev) + b1) + b2) ----
    if (apply) {
        for (int i = tid; i < DD; i += 256)
            sss[i] = (s_in[(bm*2+0)*DD + i] + s_in[(bm*2+1)*DD + i]) * (1.0f/TT);
        __syncthreads();
        if (tid < DR) {
            float acc = sb1[tid];
            for (int d = 0; d < DD; d++) acc += sw1[tid*DD + d] * sss[d];
            shh[tid] = fmaxf(acc, 0.0f);
        }
        __syncthreads();
        if (tid < DD) {
            float acc = sb2[tid];
            #pragma unroll
            for (int j = 0; j < DR; j++) acc += sw2[tid*DR + j] * shh[j];
            sa[tid] = 1.0f / (1.0f + __expf(-acc));
        }
    } else {
        for (int i = tid; i < DD; i += 256) sa[i] = 0.0f;
    }

    float acc[2][8][4];
    #pragma unroll
    for (int mt = 0; mt < 2; mt++)
        #pragma unroll
        for (int nt = 0; nt < 8; nt++) {
            acc[mt][nt][0]=0; acc[mt][nt][1]=0; acc[mt][nt][2]=0; acc[mt][nt][3]=0;
        }

    const float* up = u_in   + (size_t)bm * (DD*TT);
    const float* wp = w_prev + (size_t)bm * (DD*TT);
    float* uo = u_out + (size_t)bm * (DD*TT);

    for (int ch = 0; ch < 2; ch++) {
        int dbase = ch * 64;
        __syncthreads();   // params/sa ready (ch0) / prior mma done reading tiles (ch1)
        // weights chunk -> sB[e][dd]
        for (int i = tid; i < 128*16; i += 256) {
            int e = i >> 4, c4 = (i & 15) << 2;
            float4 v = *(const float4*)&pwA[e*DD + dbase + c4];
            float* dst = &sB[e*PADK + c4];
            dst[0] = rne_tf32(v.x); dst[1] = rne_tf32(v.y);
            dst[2] = rne_tf32(v.z); dst[3] = rne_tf32(v.w);
        }
        // stage 64-d chunk of u_cur (float4 interior + scalar halo)
        if (apply) {
            #pragma unroll
            for (int q = 0; q < 8; q++) {
                int idx = q*256 + tid;
                int dr = idx >> 5, quad = idx & 31;
                int d = dbase + dr;
                int t = t0 + quad*4;
                float av = sa[d];
                float4 u4 = *(const float4*)&up[d*TT + t];
                float4 w4 = *(const float4*)&wp[d*TT + t];
                float4 v4;
                v4.x = u4.x + w4.x*av; v4.y = u4.y + w4.y*av;
                v4.z = u4.z + w4.z*av; v4.w = u4.w + w4.w*av;
                *(float4*)&uo[d*TT + t] = v4;
                float* s = &su[dr*PADC + 2 + quad*4];
                s[0]=v4.x; s[1]=v4.y; s[2]=v4.z; s[3]=v4.w;
            }
            {   // halo: j in {0,1,130,131}
                int dr = tid >> 2, h = tid & 3;
                int d = dbase + dr;
                int j = (h < 2) ? h : 128 + h;
                int t = t0 + j - 2;
                float val = 0.0f;
                if (t >= 0 && t < TT) val = up[d*TT + t] + wp[d*TT + t]*sa[d];
                su[dr*PADC + j] = val;
            }
        } else {
            #pragma unroll
            for (int q = 0; q < 8; q++) {
                int idx = q*256 + tid;
                int dr = idx >> 5, quad = idx & 31;
                int d = dbase + dr;
                int t = t0 + quad*4;
                float4 u4 = *(const float4*)&up[d*TT + t];
                float* s = &su[dr*PADC + 2 + quad*4];
                s[0]=u4.x; s[1]=u4.y; s[2]=u4.z; s[3]=u4.w;
            }
            {
                int dr = tid >> 2, h = tid & 3;
                int d = dbase + dr;
                int j = (h < 2) ? h : 128 + h;
                int t = t0 + j - 2;
                su[dr*PADC + j] = (t >= 0 && t < TT) ? up[d*TT + t] : 0.0f;
            }
        }
        __syncthreads();
        // conv + gelu from smem -> sA[t][dd]  (4 groups of 16 rows, no syncs)
        {
            int dr = tid >> 4, c0 = tid & 15;
            #pragma unroll
            for (int g = 0; g < 4; g++) {
                int drow = g*16 + dr;          // 0..63
                int d = dbase + drow;
                const float* sr = su + drow*PADC;
                float w0 = sdw[d*KC+0], w1 = sdw[d*KC+1], w2 = sdw[d*KC+2],
                      w3 = sdw[d*KC+3], w4 = sdw[d*KC+4];
                float bb = sdb[d];
                #pragma unroll
                for (int m = 0; m < 8; m++) {
                    int j = c0 + m*16;         // local t 0..127
                    float a = bb + w0*sr[j] + w1*sr[j+1] + w2*sr[j+2]
                                 + w3*sr[j+3] + w4*sr[j+4];
                    float v = 0.5f * a * (1.0f + erff(a * 0.7071067811865475f));
                    sA[j*PADK + drow] = rne_tf32(v);
                }
            }
        }
        __syncthreads();
        // mma over this chunk
        for (int ks = 0; ks < 8; ks++) {
            int k0 = ks * 8;
            uint32_t afr[2][4];
            #pragma unroll
            for (int mt = 0; mt < 2; mt++) {
                int row = mbase + mt*16 + qr;
                afr[mt][0] = __float_as_uint(sA[row*PADK     + k0 + kb]);
                afr[mt][1] = __float_as_uint(sA[(row+8)*PADK + k0 + kb]);
                afr[mt][2] = __float_as_uint(sA[row*PADK     + k0 + 4 + kb]);
                afr[mt][3] = __float_as_uint(sA[(row+8)*PADK + k0 + 4 + kb]);
            }
            #pragma unroll
            for (int nt = 0; nt < 8; nt++) {
                int nrow = nbase + nt*8 + qr;
                uint32_t b0 = __float_as_uint(sB[nrow*PADK + k0 + kb]);
                uint32_t b1 = __float_as_uint(sB[nrow*PADK + k0 + 4 + kb]);
                mma_tf32(acc[0][nt], afr[0][0], afr[0][1], afr[0][2], afr[0][3], b0, b1);
                mma_tf32(acc[1][nt], afr[1][0], afr[1][1], afr[1][2], afr[1][3], b0, b1);
            }
        }
    }
    __syncthreads();
    // frags -> sC[e][t]
    #pragma unroll
    for (int mt = 0; mt < 2; mt++) {
        int trow = mbase + mt*16 + qr;
        #pragma unroll
        for (int nt = 0; nt < 8; nt++) {
            int e0 = nbase + nt*8 + (lane & 3)*2;
            sC[e0*PADC + trow]         = acc[mt][nt][0];
            sC[(e0+1)*PADC + trow]     = acc[mt][nt][1];
            sC[e0*PADC + trow + 8]     = acc[mt][nt][2];
            sC[(e0+1)*PADC + trow + 8] = acc[mt][nt][3];
        }
    }
    __syncthreads();
    // epilogue: bias + store w_out[e][t] + t-sum
    {
        int e = tid >> 1, half = tid & 1;
        float bv = pwb[e];
        float ssum = 0.0f;
        float* worow = w_out + (size_t)bm * (DD*TT) + (size_t)e * TT + t0 + half*64;
        const float* src = sC + e*PADC + half*64;
        #pragma unroll
        for (int i = 0; i < 16; i++) {
            float4 o;
            o.x = src[4*i+0] + bv; o.y = src[4*i+1] + bv;
            o.z = src[4*i+2] + bv; o.w = src[4*i+3] + bv;
            ssum += o.x + o.y + o.z + o.w;
            *(float4*)(worow + 4*i) = o;
        }
        ssum += __shfl_xor_sync(0xffffffffu, ssum, 1);
        if (half == 0) s_out[(bm*2 + bn)*DD + e] = ssum;
    }
}

// ---------------- SE MLP v2 (final layer only, feeds k_smean2) ----------------
__global__ void __launch_bounds__(256) k_se2(const float* __restrict__ s_in,
                      const float* __restrict__ w1, const float* __restrict__ b1,
                      const float* __restrict__ w2, const float* __restrict__ b2) {
    __shared__ float sw1[DR*129];
    __shared__ float sw2[DD*33];
    __shared__ float sb1[DR];
    __shared__ float sb2[DD];
    __shared__ float sss[8][DD];
    __shared__ float shh[8][DR];
    int tid = threadIdx.x;
    int warp = tid >> 5, lane = tid & 31;
    int bm0 = blockIdx.x * 8;

    for (int i = tid; i < DR*DD; i += 256) {
        int r = i >> 7, c = i & 127;
        sw1[r*129 + c] = w1[i];
    }
    for (int i = tid; i < DD*DR; i += 256) {
        int r = i >> 5, c = i & 31;
        sw2[r*33 + c] = w2[i];
    }
    for (int i = tid; i < DR; i += 256) sb1[i] = b1[i];
    for (int i = tid; i < DD; i += 256) sb2[i] = b2[i];
    {
        int bm = bm0 + warp;
        #pragma unroll
        for (int q = 0; q < 4; q++) {
            int d = lane + q*32;
            sss[warp][d] = (s_in[(bm*2+0)*DD + d] + s_in[(bm*2+1)*DD + d]) * (1.0f/TT);
        }
    }
    __syncthreads();
    {
        float acc = sb1[lane];
        const float* ssp = sss[warp];
        #pragma unroll 8
        for (int d = 0; d < DD; d++) acc += sw1[lane*129 + d] * ssp[d];
        shh[warp][lane] = fmaxf(acc, 0.0f);
    }
    __syncwarp();
    {
        int bm = bm0 + warp;
        const float* hp = shh[warp];
        #pragma unroll
        for (int q = 0; q < 4; q++) {
            int d = lane + q*32;
            float acc = sb2[d];
            #pragma unroll
            for (int j = 0; j < DR; j++) acc += sw2[d*33 + j] * hp[j];
            g_a[bm*DD + d] = 1.0f / (1.0f + __expf(-acc));
        }
    }
}

// ---------------- final apply + sensor mean + transpose ----------------
__global__ void k_smean2(const float* __restrict__ u, const float* __restrict__ w,
                         const float* __restrict__ a) {
    __shared__ float sm[32][257];
    int b = blockIdx.x, d0 = blockIdx.y * 32;
    int tid = threadIdx.x;
    for (int dd = 0; dd < 32; dd++) {
        int d = d0 + dd;
        float s = 0.0f;
        #pragma unroll
        for (int m = 0; m < MS; m++) {
            int bm = b*MS + m;
            size_t o = (size_t)bm*(DD*TT) + d*TT + tid;
            s += u[o] + w[o] * a[bm*DD + d];
        }
        sm[dd][tid] = s * (1.0f/MS);
    }
    __syncthreads();
    int t2 = tid >> 5, dd2 = tid & 31;
    for (int tt = t2; tt < TT; tt += 8)
        g_x2[(size_t)(b*TT + tt)*DD + d0 + dd2] = sm[dd2][tt];
}

// ---------------- NT GEMM via tf32 mma (k-chunked, R10-proven) ----------------
__global__ void __launch_bounds__(256, 2) k_gemm_nt_mma(int mode, const float* __restrict__ Bw, int K) {
    extern __shared__ float dsm[];
    float* sA = dsm;
    float* sB = dsm + 128*PADK;
    float* sC = dsm;
    const float* A; float* C; int lda, ldc;
    if (mode == 0) { A = g_x2; lda = DD;  C = g_xz;  ldc = 2*DI; }
    else           { A = g_y;  lda = DI;  C = g_out; ldc = DD;   }
    int bm0 = blockIdx.y * 128, bn0 = blockIdx.x * 128;
    int tid = threadIdx.x;
    int warp = tid >> 5, lane = tid & 31;
    int mbase = (warp & 3) * 32, nbase = (warp >> 2) * 64;
    int qr = lane >> 2, kb = lane & 3;

    float acc[2][8][4];
    #pragma unroll
    for (int mt = 0; mt < 2; mt++)
        #pragma unroll
        for (int nt = 0; nt < 8; nt++) {
            acc[mt][nt][0]=0; acc[mt][nt][1]=0; acc[mt][nt][2]=0; acc[mt][nt][3]=0;
        }

    for (int kc = 0; kc < K; kc += 64) {
        __syncthreads();
        for (int i = tid; i < 128*16; i += 256) {
            int r = i >> 4, c4 = (i & 15) << 2;
            float4 v = *(const float4*)&A[(size_t)(bm0 + r)*lda + kc + c4];
            float* dst = &sA[r*PADK + c4];
            dst[0] = rne_tf32(v.x); dst[1] = rne_tf32(v.y);
            dst[2] = rne_tf32(v.z); dst[3] = rne_tf32(v.w);
        }
        for (int i = tid; i < 128*16; i += 256) {
            int r = i >> 4, c4 = (i & 15) << 2;
            float4 v = *(const float4*)&Bw[(size_t)(bn0 + r)*K + kc + c4];
            float* dst = &sB[r*PADK + c4];
            dst[0] = rne_tf32(v.x); dst[1] = rne_tf32(v.y);
            dst[2] = rne_tf32(v.z); dst[3] = rne_tf32(v.w);
        }
        __syncthreads();
        for (int ks = 0; ks < 8; ks++) {
            int k0 = ks * 8;
            uint32_t afr[2][4];
            #pragma unroll
            for (int mt = 0; mt < 2; mt++) {
                int row = mbase + mt*16 + qr;
                afr[mt][0] = __float_as_uint(sA[row*PADK     + k0 + kb]);
                afr[mt][1] = __float_as_uint(sA[(row+8)*PADK + k0 + kb]);
                afr[mt][2] = __float_as_uint(sA[row*PADK     + k0 + 4 + kb]);
                afr[mt][3] = __float_as_uint(sA[(row+8)*PADK + k0 + 4 + kb]);
            }
            #pragma unroll
            for (int nt = 0; nt < 8; nt++) {
                int nrow = nbase + nt*8 + qr;
                uint32_t b0 = __float_as_uint(sB[nrow*PADK + k0 + kb]);
                uint32_t b1 = __float_as_uint(sB[nrow*PADK + k0 + 4 + kb]);
                mma_tf32(acc[0][nt], afr[0][0], afr[0][1], afr[0][2], afr[0][3], b0, b1);
                mma_tf32(acc[1][nt], afr[1][0], afr[1][1], afr[1][2], afr[1][3], b0, b1);
            }
        }
    }
    __syncthreads();
    #pragma unroll
    for (int mt = 0; mt < 2; mt++) {
        int mrow = mbase + mt*16 + qr;
        #pragma unroll
        for (int nt = 0; nt < 8; nt++) {
            int n0 = nbase + nt*8 + (lane & 3)*2;
            *(float2*)&sC[mrow*PADC + n0]     = make_float2(acc[mt][nt][0], acc[mt][nt][1]);
            *(float2*)&sC[(mrow+8)*PADC + n0] = make_float2(acc[mt][nt][2], acc[mt][nt][3]);
        }
    }
    __syncthreads();
    {
        int m = tid >> 1, half = tid & 1;
        float* crow = C + (size_t)(bm0 + m)*ldc + bn0 + half*64;
        const float* src = sC + m*PADC + half*64;
        #pragma unroll
        for (int i = 0; i < 16; i++)
            *(float4*)(crow + 4*i) = *(const float4*)(src + 4*i);
    }
}

// ---------------- mamba: causal depthwise conv + silu ----------------
__global__ void k_convsilu(const float* __restrict__ cw, const float* __restrict__ cb) {
    int idx = blockIdx.x * blockDim.x + threadIdx.x;
    if (idx >= BT*DI) return;
    int c = idx & (DI-1);
    int t = (idx >> 8) & (TT-1);
    int b = idx >> 16;
    float acc = cb[c];
    #pragma unroll
    for (int j = 0; j < DCV; j++) {
        int tt = t - 3 + j;
        if (tt >= 0) acc += cw[c*DCV + j] * g_xz[(size_t)(b*TT + tt)*(2*DI) + c];
    }
    g_xc[idx] = acc / (1.0f + __expf(-acc));
}

// ---------------- mamba: dbl = xc @ xproj^T, fused dt ----------------
__global__ void k_dblt(const float* __restrict__ xp,
                       const float* __restrict__ dtw, const float* __restrict__ dtb) {
    __shared__ float sx[32][DI+1];
    __shared__ float sd[32][RKD];
    int t0 = blockIdx.x * 32;
    int tid = threadIdx.x;
    for (int i = tid; i < 32*DI; i += 256) {
        int tt = i >> 8, c = i & (DI-1);
        sx[tt][c] = g_xc[(size_t)(t0 + tt)*DI + c];
    }
    __syncthreads();
    for (int o = tid; o < 32*40; o += 256) {
        int tt = o & 31, k = o >> 5;
        const float* wrow = xp + k*DI;
        float acc = 0.0f;
        #pragma unroll 8
        for (int c = 0; c < DI; c++) acc += wrow[c] * sx[tt][c];
        if (k < RKD) sd[tt][k] = acc;
        else g_dbl[(size_t)(t0 + tt)*40 + k] = acc;
    }
    __syncthreads();
    {
        int c = tid;
        float wreg[RKD];
        #pragma unroll
        for (int r = 0; r < RKD; r++) wreg[r] = dtw[c*RKD + r];
        float bb = dtb[c];
        for (int tt = 0; tt < 32; tt++) {
            float acc = bb;
            #pragma unroll
            for (int r = 0; r < RKD; r++) acc += wreg[r] * sd[tt][r];
            g_dt[(size_t)(t0 + tt)*DI + c] = (acc > 20.0f) ? acc : log1pf(__expf(acc));
        }
    }
}

// ---------------- mamba: selective scan + gate (prefetched) ----------------
__global__ void k_scan(const float* __restrict__ Alog, const float* __restrict__ Dp) {
    __shared__ float sBC[TT][32];
    int b = blockIdx.y;
    int c = blockIdx.x * blockDim.x + threadIdx.x;
    for (int i = threadIdx.x; i < TT*32; i += blockDim.x) {
        int tt = i >> 5, j = i & 31;
        sBC[tt][j] = g_dbl[(size_t)(b*TT + tt)*40 + 8 + j];
    }
    __syncthreads();
    float Av[DSN];
    #pragma unroll
    for (int s = 0; s < DSN; s++) Av[s] = -__expf(Alog[c*DSN + s]);
    float A0 = Av[0];
    bool structured = true;
    #pragma unroll
    for (int s = 0; s < DSN; s++)
        if (fabsf(Av[s] - (float)(s+1)*A0) > 1e-4f * fabsf(Av[s])) structured = false;
    float h[DSN];
    #pragma unroll
    for (int s = 0; s < DSN; s++) h[s] = 0.0f;
    float dpc = Dp[c];
    size_t bt0 = (size_t)(b*TT);
    float dtv = g_dt[bt0*DI + c];
    float xcv = g_xc[bt0*DI + c];
    float zv  = g_xz[bt0*(2*DI) + DI + c];
    for (int t = 0; t < TT; t++) {
        float dtn = 0.0f, xcn = 0.0f, zn = 0.0f;
        if (t < TT-1) {
            size_t btn = bt0 + t + 1;
            dtn = g_dt[btn*DI + c];
            xcn = g_xc[btn*DI + c];
            zn  = g_xz[btn*(2*DI) + DI + c];
        }
        float dtxc = dtv * xcv;
        float y = 0.0f;
        if (structured) {
            float r = __expf(dtv * A0);
            float p = 1.0f;
            #pragma unroll
            for (int s = 0; s < DSN; s++) {
                p *= r;
                h[s] = p*h[s] + dtxc*sBC[t][s];
                y += h[s]*sBC[t][16+s];
            }
        } else {
            #pragma unroll
            for (int s = 0; s < DSN; s++) {
                float dA = __expf(dtv * Av[s]);
                h[s] = dA*h[s] + dtxc*sBC[t][s];
                y += h[s]*sBC[t][16+s];
            }
        }
        float yv = y + dpc*xcv;
        yv = yv * (zv / (1.0f + __expf(-zv)));
        g_y[(bt0 + t)*DI + c] = yv;
        dtv = dtn; xcv = xcn; zv = zn;
    }
}

// ---------------- residual + layernorm ----------------
__global__ void k_ln(const float* __restrict__ g, const float* __restrict__ bta) {
    __shared__ float red[4];
    int bt = blockIdx.x, d = threadIdx.x;
    float v = g_x2[(size_t)bt*DD + d] + g_out[(size_t)bt*DD + d];
    float s = v;
    #pragma unroll
    for (int o = 16; o > 0; o >>= 1) s += __shfl_xor_sync(0xffffffffu, s, o);
    if ((d & 31) == 0) red[d >> 5] = s;
    __syncthreads();
    float mean = (red[0] + red[1] + red[2] + red[3]) * (1.0f/DD);
    float dv = v - mean;
    float q = dv * dv;
    #pragma unroll
    for (int o = 16; o > 0; o >>= 1) q += __shfl_xor_sync(0xffffffffu, q, o);
    __syncthreads();
    if ((d & 31) == 0) red[d >> 5] = q;
    __syncthreads();
    float var = (red[0] + red[1] + red[2] + red[3]) * (1.0f/DD);
    g_x2[(size_t)bt*DD + d] = dv * rsqrtf(var + 1e-5f) * g[d] + bta[d];
}

// ---------------- xflat transpose into d_out ----------------
__global__ void k_xflat2(float* __restrict__ out) {
    __shared__ float sm[32][257];
    int b = blockIdx.x, d0 = blockIdx.y * 32;
    int tid = threadIdx.x;
    int tb = tid >> 5, dd = tid & 31;
    for (int t = tb; t < TT; t += 8)
        sm[dd][t] = g_x2[(size_t)(b*TT + t)*DD + d0 + dd];
    __syncthreads();
    for (int dd2 = 0; dd2 < 32; dd2++)
        out[(size_t)b*(DD*TT) + (d0+dd2)*TT + tid] = sm[dd2][tid];
}

// ---------------- pred head ----------------
__global__ void k_pred(const float* __restrict__ xflat, const float* __restrict__ fcw,
                       const float* __restrict__ fcb, float* __restrict__ pred) {
    __shared__ float red[8];
    int c = blockIdx.x, b = blockIdx.y, tid = threadIdx.x;
    const float4* x4 = (const float4*)(xflat + (size_t)b * (DD*TT));
    const float4* w4 = (const float4*)(fcw + (size_t)c * (DD*TT));
    float s = 0.0f;
    for (int i = tid; i < DD*TT/4; i += blockDim.x) {
        float4 a = x4[i], w = w4[i];
        s += a.x*w.x + a.y*w.y + a.z*w.z + a.w*w.w;
    }
    #pragma unroll
    for (int o = 16; o > 0; o >>= 1) s += __shfl_xor_sync(0xffffffffu, s, o);
    if ((tid & 31) == 0) red[tid >> 5] = s;
    __syncthreads();
    if (tid == 0) {
        float tot = 0.0f;
        for (int i = 0; i < (int)(blockDim.x >> 5); i++) tot += red[i];
        pred[b*CC + c] = tot + fcb[c];
    }
}

// ---------------- launch ----------------
extern "C" void kernel_launch(void* const* d_in, const int* in_sizes, int n_in,
                              void* d_out, int out_size) {
    const float* inputs    = (const float*)d_in[0];
    const float* emb_w     = (const float*)d_in[1];
    const float* emb_b     = (const float*)d_in[2];
    const float* blk_dw_w  = (const float*)d_in[3];
    const float* blk_dw_b  = (const float*)d_in[4];
    const float* blk_pw_w  = (const float*)d_in[5];
    const float* blk_pw_b  = (const float*)d_in[6];
    const float* blk_se_w1 = (const float*)d_in[7];
    const float* blk_se_b1 = (const float*)d_in[8];
    const float* blk_se_w2 = (const float*)d_in[9];
    const float* blk_se_b2 = (const float*)d_in[10];
    const float* mam_in_w  = (const float*)d_in[11];
    const float* mam_conv_w= (const float*)d_in[12];
    const float* mam_conv_b= (const float*)d_in[13];
    const float* mam_xproj = (const float*)d_in[14];
    const float* mam_dt_w  = (const float*)d_in[15];
    const float* mam_dt_b  = (const float*)d_in[16];
    const float* mam_Alog  = (const float*)d_in[17];
    const float* mam_D     = (const float*)d_in[18];
    const float* mam_out_w = (const float*)d_in[19];
    const float* ln_g      = (const float*)d_in[20];
    const float* ln_b      = (const float*)d_in[21];
    const float* fc_w      = (const float*)d_in[22];
    const float* fc_b      = (const float*)d_in[23];
    float* out = (float*)d_out;

    float *uA, *uB, *wA, *wB, *s2a, *s2b, *aa;
    cudaGetSymbolAddress((void**)&uA, g_uA);
    cudaGetSymbolAddress((void**)&uB, g_uB);
    cudaGetSymbolAddress((void**)&wA, g_wA);
    cudaGetSymbolAddress((void**)&wB, g_wB);
    cudaGetSymbolAddress((void**)&s2a, g_s2a);
    cudaGetSymbolAddress((void**)&s2b, g_s2b);
    cudaGetSymbolAddress((void**)&aa, g_a);

    cudaFuncSetAttribute(k_block_mma,   cudaFuncAttributeMaxDynamicSharedMemorySize, SMEM_BLOCK);
    cudaFuncSetAttribute(k_gemm_nt_mma, cudaFuncAttributeMaxDynamicSharedMemorySize, SMEM_GEMM);

    k_emb<<<BMR, 256>>>(inputs, emb_w, emb_b);

    // block 0: read uA -> wA (no apply), t-sums -> s2a
    k_block_mma<<<dim3(2, BMR), 256, SMEM_BLOCK>>>(uA, wA, s2a, uB, wA, s2a,
        blk_dw_w + 0*DD*KC, blk_dw_b + 0*DD, blk_pw_w + 0*DD*DD, blk_pw_b + 0*DD,
        blk_se_w1, blk_se_b1, blk_se_w2, blk_se_b2, 0);
    // block 1: SE(layer0, s2a) in-CTA; read uA,wA -> u1 into uB, w1 into wB; sums -> s2b
    k_block_mma<<<dim3(2, BMR), 256, SMEM_BLOCK>>>(uA, wA, s2a, uB, wB, s2b,
        blk_dw_w + 1*DD*KC, blk_dw_b + 1*DD, blk_pw_w + 1*DD*DD, blk_pw_b + 1*DD,
        blk_se_w1 + 0*DR*DD, blk_se_b1 + 0*DR, blk_se_w2 + 0*DD*DR, blk_se_b2 + 0*DD, 1);
    // block 2: SE(layer1, s2b) in-CTA; read uB,wB -> u2 into uA, w2 into wA; sums -> s2a
    k_block_mma<<<dim3(2, BMR), 256, SMEM_BLOCK>>>(uB, wB, s2b, uA, wA, s2a,
        blk_dw_w + 2*DD*KC, blk_dw_b + 2*DD, blk_pw_w + 2*DD*DD, blk_pw_b + 2*DD,
        blk_se_w1 + 1*DR*DD, blk_se_b1 + 1*DR, blk_se_w2 + 1*DD*DR, blk_se_b2 + 1*DD, 1);
    // SE(layer2) -> g_a for final apply
    k_se2<<<BMR/8, 256>>>(s2a, blk_se_w1 + 2*DR*DD, blk_se_b1 + 2*DR,
                          blk_se_w2 + 2*DD*DR, blk_se_b2 + 2*DD);

    k_smean2<<<dim3(NB, DD/32), 256>>>(uA, wA, aa);

    for (int i = 0; i < NMB; i++) {
        k_gemm_nt_mma<<<dim3(4, BT/128), 256, SMEM_GEMM>>>(0, mam_in_w + (size_t)i*2*DI*DD, DD);
        k_convsilu<<<(BT*DI)/256, 256>>>(mam_conv_w + i*DI*DCV, mam_conv_b + i*DI);
        k_dblt<<<BT/32, 256>>>(mam_xproj + (size_t)i*40*DI, mam_dt_w + i*DI*RKD, mam_dt_b + i*DI);
        k_scan<<<dim3(DI/128, NB), 128>>>(mam_Alog + i*DI*DSN, mam_D + i*DI);
        k_gemm_nt_mma<<<dim3(1, BT/128), 256, SMEM_GEMM>>>(1, mam_out_w + (size_t)i*DD*DI, DI);
        k_ln<<<BT, DD>>>(ln_g + i*DD, ln_b + i*DD);
    }

    k_xflat2<<<dim3(NB, DD/32), 256>>>(out);
    k_pred<<<dim3(CC, NB), 256>>>(out, fc_w, fc_b, out + (size_t)NB*DD*TT);
}

// round 15
// speedup vs baseline: 1.0763x; 1.0763x over previous
#include <cuda_runtime.h>
#include <math.h>
#include <stdint.h>

// ---------------- problem constants ----------------
#define NB   64
#define LL   2048
#define MS   12
#define DD   128
#define PP   16
#define SSTR 8
#define TT   256
#define KC   5
#define DR   32
#define NMB  2
#define DI   256
#define DCV  4
#define DSN  16
#define RKD  8
#define CC   18
#define BMR  768     // NB*MS
#define BT   16384   // NB*TT

#define PADK 68      // 64 + 4 pad (k-chunk tiles)
#define PADC 132     // 128 + 4 pad (C tile / staging rows)

// ---------------- scratch (device globals, no allocs) ----------------
__device__ float g_uA [BMR*DD*TT];
__device__ float g_uB [BMR*DD*TT];
__device__ float g_wA [BMR*DD*TT];
__device__ float g_wB [BMR*DD*TT];
__device__ float g_s2 [BMR*2*DD];
__device__ float g_a  [BMR*DD];
__device__ float g_x2 [BT*DD];
__device__ float g_xz [BT*2*DI];
__device__ float g_xc [BT*DI];
__device__ float g_dbl[BT*40];
__device__ float g_dt [BT*DI];
__device__ float g_y  [BT*DI];
__device__ float g_out[BT*DD];

// ---------------- helpers ----------------
__device__ __forceinline__ float rne_tf32(float x) {
    uint32_t u = __float_as_uint(x);
    u += 0xFFFu + ((u >> 13) & 1u);
    u &= 0xFFFFE000u;
    return __uint_as_float(u);
}

__device__ __forceinline__ void mma_tf32(float c[4],
    uint32_t a0, uint32_t a1, uint32_t a2, uint32_t a3,
    uint32_t b0, uint32_t b1)
{
    asm volatile(
        "mma.sync.aligned.m16n8k8.row.col.f32.tf32.tf32.f32 "
        "{%0,%1,%2,%3}, {%4,%5,%6,%7}, {%8,%9}, {%0,%1,%2,%3};"
        : "+f"(c[0]), "+f"(c[1]), "+f"(c[2]), "+f"(c[3])
        : "r"(a0), "r"(a1), "r"(a2), "r"(a3), "r"(b0), "r"(b1));
}

// dyn smem: sB[128][PADK] + sA[128][PADK] + su[64][PADC]
#define SMEM_BLOCK ((2*128*PADK + 64*PADC) * 4)   // 103424 B
#define SMEM_GEMM  (2 * 128 * PADK * 4)           // 69632 B

// ---------------- stage 1: embedding conv (register-held inputs) ----------------
__global__ void k_emb(const float* __restrict__ xin,
                      const float* __restrict__ w,
                      const float* __restrict__ bias) {
    __shared__ float srow[LL];
    __shared__ float sw[DD*PP];
    __shared__ float sb[DD];
    int bm = blockIdx.x;
    int b = bm / MS, m = bm % MS;
    const float* xp = xin + (size_t)b * (LL*MS) + m;
    for (int l = threadIdx.x; l < LL; l += blockDim.x) srow[l] = xp[(size_t)l * MS];
    for (int i = threadIdx.x; i < DD*PP; i += blockDim.x) sw[i] = w[i];
    for (int i = threadIdx.x; i < DD; i += blockDim.x) sb[i] = bias[i];
    __syncthreads();
    int t = threadIdx.x;
    int base = t * SSTR - 4;
    float x[PP];
    #pragma unroll
    for (int p = 0; p < PP; p++) {
        int l = base + p;
        x[p] = (l >= 0 && l < LL) ? srow[l] : 0.0f;
    }
    float* outp = g_uA + (size_t)bm * (DD*TT);
    for (int d = 0; d < DD; d++) {
        float acc = sb[d];
        #pragma unroll
        for (int p = 0; p < PP; p++) acc += sw[d*PP + p] * x[p];
        outp[d*TT + t] = acc;
    }
}

// ---------------- fused block kernel: float4 staging + tf32 mma (R10-proven) ----------------
// C[t][e] = sum_d V[t][d] * W[e][d];  V = gelu(dwconv(u [+ w_prev*a]))
__global__ void __launch_bounds__(256, 2) k_block_mma(
    const float* __restrict__ u_in, const float* __restrict__ w_prev,
    const float* __restrict__ a_prev, float* __restrict__ u_out,
    float* __restrict__ w_out, float* __restrict__ s_out,
    const float* __restrict__ dww, const float* __restrict__ dwb,
    const float* __restrict__ pwA, const float* __restrict__ pwb,
    int apply)
{
    extern __shared__ float dsm[];
    float* sB = dsm;                 // weights [e=128][64] pad PADK
    float* sA = dsm + 128*PADK;      // v       [t=128][64] pad PADK
    float* su = dsm + 2*128*PADK;    // u stage [64 d-rows][PADC]
    float* sC = dsm;                 // reuse sB+sA: [e=128][t] pad PADC
    __shared__ float sdw[DD*KC];
    __shared__ float sdb[DD];
    __shared__ float sa[DD];

    int bm = blockIdx.y, bn = blockIdx.x, t0 = bn * 128;
    int tid = threadIdx.x;
    int warp = tid >> 5, lane = tid & 31;
    int mbase = (warp & 3) * 32, nbase = (warp >> 2) * 64;
    int qr = lane >> 2, kb = lane & 3;

    for (int i = tid; i < DD*KC; i += 256) sdw[i] = dww[i];
    for (int i = tid; i < DD; i += 256) {
        sdb[i] = dwb[i];
        sa[i]  = apply ? a_prev[bm*DD + i] : 0.0f;
    }

    float acc[2][8][4];
    #pragma unroll
    for (int mt = 0; mt < 2; mt++)
        #pragma unroll
        for (int nt = 0; nt < 8; nt++) {
            acc[mt][nt][0]=0; acc[mt][nt][1]=0; acc[mt][nt][2]=0; acc[mt][nt][3]=0;
        }

    const float* up = u_in   + (size_t)bm * (DD*TT);
    const float* wp = w_prev + (size_t)bm * (DD*TT);
    float* uo = u_out + (size_t)bm * (DD*TT);

    for (int ch = 0; ch < 2; ch++) {
        int dbase = ch * 64;
        __syncthreads();   // params ready (ch0) / prior mma done reading tiles (ch1)
        // weights chunk -> sB[e][dd]
        for (int i = tid; i < 128*16; i += 256) {
            int e = i >> 4, c4 = (i & 15) << 2;
            float4 v = *(const float4*)&pwA[e*DD + dbase + c4];
            float* dst = &sB[e*PADK + c4];
            dst[0] = rne_tf32(v.x); dst[1] = rne_tf32(v.y);
            dst[2] = rne_tf32(v.z); dst[3] = rne_tf32(v.w);
        }
        // stage 64-d chunk of u_cur (float4 interior + scalar halo)
        if (apply) {
            #pragma unroll
            for (int q = 0; q < 8; q++) {
                int idx = q*256 + tid;
                int dr = idx >> 5, quad = idx & 31;
                int d = dbase + dr;
                int t = t0 + quad*4;
                float av = sa[d];
                float4 u4 = *(const float4*)&up[d*TT + t];
                float4 w4 = *(const float4*)&wp[d*TT + t];
                float4 v4;
                v4.x = u4.x + w4.x*av; v4.y = u4.y + w4.y*av;
                v4.z = u4.z + w4.z*av; v4.w = u4.w + w4.w*av;
                *(float4*)&uo[d*TT + t] = v4;
                float* s = &su[dr*PADC + 2 + quad*4];
                s[0]=v4.x; s[1]=v4.y; s[2]=v4.z; s[3]=v4.w;
            }
            {   // halo: j in {0,1,130,131}
                int dr = tid >> 2, h = tid & 3;
                int d = dbase + dr;
                int j = (h < 2) ? h : 128 + h;
                int t = t0 + j - 2;
                float val = 0.0f;
                if (t >= 0 && t < TT) val = up[d*TT + t] + wp[d*TT + t]*sa[d];
                su[dr*PADC + j] = val;
            }
        } else {
            #pragma unroll
            for (int q = 0; q < 8; q++) {
                int idx = q*256 + tid;
                int dr = idx >> 5, quad = idx & 31;
                int d = dbase + dr;
                int t = t0 + quad*4;
                float4 u4 = *(const float4*)&up[d*TT + t];
                float* s = &su[dr*PADC + 2 + quad*4];
                s[0]=u4.x; s[1]=u4.y; s[2]=u4.z; s[3]=u4.w;
            }
            {
                int dr = tid >> 2, h = tid & 3;
                int d = dbase + dr;
                int j = (h < 2) ? h : 128 + h;
                int t = t0 + j - 2;
                su[dr*PADC + j] = (t >= 0 && t < TT) ? up[d*TT + t] : 0.0f;
            }
        }
        __syncthreads();
        // conv + gelu from smem -> sA[t][dd]  (4 groups of 16 rows, no syncs)
        {
            int dr = tid >> 4, c0 = tid & 15;
            #pragma unroll
            for (int g = 0; g < 4; g++) {
                int drow = g*16 + dr;          // 0..63
                int d = dbase + drow;
                const float* sr = su + drow*PADC;
                float w0 = sdw[d*KC+0], w1 = sdw[d*KC+1], w2 = sdw[d*KC+2],
                      w3 = sdw[d*KC+3], w4 = sdw[d*KC+4];
                float bb = sdb[d];
                #pragma unroll
                for (int m = 0; m < 8; m++) {
                    int j = c0 + m*16;         // local t 0..127
                    float a = bb + w0*sr[j] + w1*sr[j+1] + w2*sr[j+2]
                                 + w3*sr[j+3] + w4*sr[j+4];
                    float v = 0.5f * a * (1.0f + erff(a * 0.7071067811865475f));
                    sA[j*PADK + drow] = rne_tf32(v);
                }
            }
        }
        __syncthreads();
        // mma over this chunk
        for (int ks = 0; ks < 8; ks++) {
            int k0 = ks * 8;
            uint32_t afr[2][4];
            #pragma unroll
            for (int mt = 0; mt < 2; mt++) {
                int row = mbase + mt*16 + qr;
                afr[mt][0] = __float_as_uint(sA[row*PADK     + k0 + kb]);
                afr[mt][1] = __float_as_uint(sA[(row+8)*PADK + k0 + kb]);
                afr[mt][2] = __float_as_uint(sA[row*PADK     + k0 + 4 + kb]);
                afr[mt][3] = __float_as_uint(sA[(row+8)*PADK + k0 + 4 + kb]);
            }
            #pragma unroll
            for (int nt = 0; nt < 8; nt++) {
                int nrow = nbase + nt*8 + qr;
                uint32_t b0 = __float_as_uint(sB[nrow*PADK + k0 + kb]);
                uint32_t b1 = __float_as_uint(sB[nrow*PADK + k0 + 4 + kb]);
                mma_tf32(acc[0][nt], afr[0][0], afr[0][1], afr[0][2], afr[0][3], b0, b1);
                mma_tf32(acc[1][nt], afr[1][0], afr[1][1], afr[1][2], afr[1][3], b0, b1);
            }
        }
    }
    __syncthreads();
    // frags -> sC[e][t]
    #pragma unroll
    for (int mt = 0; mt < 2; mt++) {
        int trow = mbase + mt*16 + qr;
        #pragma unroll
        for (int nt = 0; nt < 8; nt++) {
            int e0 = nbase + nt*8 + (lane & 3)*2;
            sC[e0*PADC + trow]         = acc[mt][nt][0];
            sC[(e0+1)*PADC + trow]     = acc[mt][nt][1];
            sC[e0*PADC + trow + 8]     = acc[mt][nt][2];
            sC[(e0+1)*PADC + trow + 8] = acc[mt][nt][3];
        }
    }
    __syncthreads();
    // epilogue: bias + store w_out[e][t] + t-sum
    {
        int e = tid >> 1, half = tid & 1;
        float bv = pwb[e];
        float ssum = 0.0f;
        float* worow = w_out + (size_t)bm * (DD*TT) + (size_t)e * TT + t0 + half*64;
        const float* src = sC + e*PADC + half*64;
        #pragma unroll
        for (int i = 0; i < 16; i++) {
            float4 o;
            o.x = src[4*i+0] + bv; o.y = src[4*i+1] + bv;
            o.z = src[4*i+2] + bv; o.w = src[4*i+3] + bv;
            ssum += o.x + o.y + o.z + o.w;
            *(float4*)(worow + 4*i) = o;
        }
        ssum += __shfl_xor_sync(0xffffffffu, ssum, 1);
        if (half == 0) s_out[(bm*2 + bn)*DD + e] = ssum;
    }
}

// ---------------- SE MLP v2: 8 bm per block, warp-parallel ----------------
__global__ void __launch_bounds__(256) k_se2(const float* __restrict__ w1, const float* __restrict__ b1,
                      const float* __restrict__ w2, const float* __restrict__ b2) {
    __shared__ float sw1[DR*129];
    __shared__ float sw2[DD*33];
    __shared__ float sb1[DR];
    __shared__ float sb2[DD];
    __shared__ float sss[8][DD];
    __shared__ float shh[8][DR];
    int tid = threadIdx.x;
    int warp = tid >> 5, lane = tid & 31;
    int bm0 = blockIdx.x * 8;

    for (int i = tid; i < DR*DD; i += 256) {
        int r = i >> 7, c = i & 127;
        sw1[r*129 + c] = w1[i];
    }
    for (int i = tid; i < DD*DR; i += 256) {
        int r = i >> 5, c = i & 31;
        sw2[r*33 + c] = w2[i];
    }
    for (int i = tid; i < DR; i += 256) sb1[i] = b1[i];
    for (int i = tid; i < DD; i += 256) sb2[i] = b2[i];
    {
        int bm = bm0 + warp;
        #pragma unroll
        for (int q = 0; q < 4; q++) {
            int d = lane + q*32;
            sss[warp][d] = (g_s2[(bm*2+0)*DD + d] + g_s2[(bm*2+1)*DD + d]) * (1.0f/TT);
        }
    }
    __syncthreads();
    {
        float acc = sb1[lane];
        const float* ssp = sss[warp];
        #pragma unroll 8
        for (int d = 0; d < DD; d++) acc += sw1[lane*129 + d] * ssp[d];
        shh[warp][lane] = fmaxf(acc, 0.0f);
    }
    __syncwarp();
    {
        int bm = bm0 + warp;
        const float* hp = shh[warp];
        #pragma unroll
        for (int q = 0; q < 4; q++) {
            int d = lane + q*32;
            float acc = sb2[d];
            #pragma unroll
            for (int j = 0; j < DR; j++) acc += sw2[d*33 + j] * hp[j];
            g_a[bm*DD + d] = 1.0f / (1.0f + __expf(-acc));
        }
    }
}

// ---------------- final apply + sensor mean + transpose (float4 loads) ----------------
__global__ void k_smean2(const float* __restrict__ u, const float* __restrict__ w,
                         const float* __restrict__ a) {
    __shared__ float sm[32][257];
    int b = blockIdx.x, d0 = blockIdx.y * 32;
    int tid = threadIdx.x;
    int tq = tid & 63;            // t quad: t = tq*4
    int dg = tid >> 6;            // 0..3
    #pragma unroll
    for (int dd = 0; dd < 8; dd++) {
        int drow = dg*8 + dd;
        int d = d0 + drow;
        float sx = 0.0f, sy = 0.0f, sz = 0.0f, sw_ = 0.0f;
        #pragma unroll
        for (int m = 0; m < MS; m++) {
            int bm = b*MS + m;
            size_t o = (size_t)bm*(DD*TT) + (size_t)d*TT + tq*4;
            float4 u4 = *(const float4*)&u[o];
            float4 w4 = *(const float4*)&w[o];
            float av = a[bm*DD + d];
            sx += u4.x + w4.x*av; sy += u4.y + w4.y*av;
            sz += u4.z + w4.z*av; sw_ += u4.w + w4.w*av;
        }
        float* dst = &sm[drow][tq*4];
        dst[0] = sx*(1.0f/MS); dst[1] = sy*(1.0f/MS);
        dst[2] = sz*(1.0f/MS); dst[3] = sw_*(1.0f/MS);
    }
    __syncthreads();
    int t2 = tid >> 5, dd2 = tid & 31;
    for (int tt = t2; tt < TT; tt += 8)
        g_x2[(size_t)(b*TT + tt)*DD + d0 + dd2] = sm[dd2][tt];
}

// ---------------- NT GEMM via tf32 mma (k-chunked, R10-proven) ----------------
__global__ void __launch_bounds__(256, 2) k_gemm_nt_mma(int mode, const float* __restrict__ Bw, int K) {
    extern __shared__ float dsm[];
    float* sA = dsm;
    float* sB = dsm + 128*PADK;
    float* sC = dsm;
    const float* A; float* C; int lda, ldc;
    if (mode == 0) { A = g_x2; lda = DD;  C = g_xz;  ldc = 2*DI; }
    else           { A = g_y;  lda = DI;  C = g_out; ldc = DD;   }
    int bm0 = blockIdx.y * 128, bn0 = blockIdx.x * 128;
    int tid = threadIdx.x;
    int warp = tid >> 5, lane = tid & 31;
    int mbase = (warp & 3) * 32, nbase = (warp >> 2) * 64;
    int qr = lane >> 2, kb = lane & 3;

    float acc[2][8][4];
    #pragma unroll
    for (int mt = 0; mt < 2; mt++)
        #pragma unroll
        for (int nt = 0; nt < 8; nt++) {
            acc[mt][nt][0]=0; acc[mt][nt][1]=0; acc[mt][nt][2]=0; acc[mt][nt][3]=0;
        }

    for (int kc = 0; kc < K; kc += 64) {
        __syncthreads();
        for (int i = tid; i < 128*16; i += 256) {
            int r = i >> 4, c4 = (i & 15) << 2;
            float4 v = *(const float4*)&A[(size_t)(bm0 + r)*lda + kc + c4];
            float* dst = &sA[r*PADK + c4];
            dst[0] = rne_tf32(v.x); dst[1] = rne_tf32(v.y);
            dst[2] = rne_tf32(v.z); dst[3] = rne_tf32(v.w);
        }
        for (int i = tid; i < 128*16; i += 256) {
            int r = i >> 4, c4 = (i & 15) << 2;
            float4 v = *(const float4*)&Bw[(size_t)(bn0 + r)*K + kc + c4];
            float* dst = &sB[r*PADK + c4];
            dst[0] = rne_tf32(v.x); dst[1] = rne_tf32(v.y);
            dst[2] = rne_tf32(v.z); dst[3] = rne_tf32(v.w);
        }
        __syncthreads();
        for (int ks = 0; ks < 8; ks++) {
            int k0 = ks * 8;
            uint32_t afr[2][4];
            #pragma unroll
            for (int mt = 0; mt < 2; mt++) {
                int row = mbase + mt*16 + qr;
                afr[mt][0] = __float_as_uint(sA[row*PADK     + k0 + kb]);
                afr[mt][1] = __float_as_uint(sA[(row+8)*PADK + k0 + kb]);
                afr[mt][2] = __float_as_uint(sA[row*PADK     + k0 + 4 + kb]);
                afr[mt][3] = __float_as_uint(sA[(row+8)*PADK + k0 + 4 + kb]);
            }
            #pragma unroll
            for (int nt = 0; nt < 8; nt++) {
                int nrow = nbase + nt*8 + qr;
                uint32_t b0 = __float_as_uint(sB[nrow*PADK + k0 + kb]);
                uint32_t b1 = __float_as_uint(sB[nrow*PADK + k0 + 4 + kb]);
                mma_tf32(acc[0][nt], afr[0][0], afr[0][1], afr[0][2], afr[0][3], b0, b1);
                mma_tf32(acc[1][nt], afr[1][0], afr[1][1], afr[1][2], afr[1][3], b0, b1);
            }
        }
    }
    __syncthreads();
    #pragma unroll
    for (int mt = 0; mt < 2; mt++) {
        int mrow = mbase + mt*16 + qr;
        #pragma unroll
        for (int nt = 0; nt < 8; nt++) {
            int n0 = nbase + nt*8 + (lane & 3)*2;
            *(float2*)&sC[mrow*PADC + n0]     = make_float2(acc[mt][nt][0], acc[mt][nt][1]);
            *(float2*)&sC[(mrow+8)*PADC + n0] = make_float2(acc[mt][nt][2], acc[mt][nt][3]);
        }
    }
    __syncthreads();
    {
        int m = tid >> 1, half = tid & 1;
        float* crow = C + (size_t)(bm0 + m)*ldc + bn0 + half*64;
        const float* src = sC + m*PADC + half*64;
        #pragma unroll
        for (int i = 0; i < 16; i++)
            *(float4*)(crow + 4*i) = *(const float4*)(src + 4*i);
    }
}

// ---------------- mamba: causal depthwise conv + silu ----------------
__global__ void k_convsilu(const float* __restrict__ cw, const float* __restrict__ cb) {
    int idx = blockIdx.x * blockDim.x + threadIdx.x;
    if (idx >= BT*DI) return;
    int c = idx & (DI-1);
    int t = (idx >> 8) & (TT-1);
    int b = idx >> 16;
    float acc = cb[c];
    #pragma unroll
    for (int j = 0; j < DCV; j++) {
        int tt = t - 3 + j;
        if (tt >= 0) acc += cw[c*DCV + j] * g_xz[(size_t)(b*TT + tt)*(2*DI) + c];
    }
    g_xc[idx] = acc / (1.0f + __expf(-acc));
}

// ---------------- mamba: dbl = xc @ xproj^T, fused dt ----------------
__global__ void k_dblt(const float* __restrict__ xp,
                       const float* __restrict__ dtw, const float* __restrict__ dtb) {
    __shared__ float sx[32][DI+1];
    __shared__ float sd[32][RKD];
    int t0 = blockIdx.x * 32;
    int tid = threadIdx.x;
    for (int i = tid; i < 32*DI; i += 256) {
        int tt = i >> 8, c = i & (DI-1);
        sx[tt][c] = g_xc[(size_t)(t0 + tt)*DI + c];
    }
    __syncthreads();
    for (int o = tid; o < 32*40; o += 256) {
        int tt = o & 31, k = o >> 5;
        const float* wrow = xp + k*DI;
        float acc = 0.0f;
        #pragma unroll 8
        for (int c = 0; c < DI; c++) acc += wrow[c] * sx[tt][c];
        if (k < RKD) sd[tt][k] = acc;
        else g_dbl[(size_t)(t0 + tt)*40 + k] = acc;
    }
    __syncthreads();
    {
        int c = tid;
        float wreg[RKD];
        #pragma unroll
        for (int r = 0; r < RKD; r++) wreg[r] = dtw[c*RKD + r];
        float bb = dtb[c];
        for (int tt = 0; tt < 32; tt++) {
            float acc = bb;
            #pragma unroll
            for (int r = 0; r < RKD; r++) acc += wreg[r] * sd[tt][r];
            g_dt[(size_t)(t0 + tt)*DI + c] = (acc > 20.0f) ? acc : log1pf(__expf(acc));
        }
    }
}

// ---------------- mamba: selective scan + gate (prefetched) ----------------
__global__ void k_scan(const float* __restrict__ Alog, const float* __restrict__ Dp) {
    __shared__ float sBC[TT][32];
    int b = blockIdx.y;
    int c = blockIdx.x * blockDim.x + threadIdx.x;
    for (int i = threadIdx.x; i < TT*32; i += blockDim.x) {
        int tt = i >> 5, j = i & 31;
        sBC[tt][j] = g_dbl[(size_t)(b*TT + tt)*40 + 8 + j];
    }
    __syncthreads();
    float Av[DSN];
    #pragma unroll
    for (int s = 0; s < DSN; s++) Av[s] = -__expf(Alog[c*DSN + s]);
    float A0 = Av[0];
    bool structured = true;
    #pragma unroll
    for (int s = 0; s < DSN; s++)
        if (fabsf(Av[s] - (float)(s+1)*A0) > 1e-4f * fabsf(Av[s])) structured = false;
    float h[DSN];
    #pragma unroll
    for (int s = 0; s < DSN; s++) h[s] = 0.0f;
    float dpc = Dp[c];
    size_t bt0 = (size_t)(b*TT);
    float dtv = g_dt[bt0*DI + c];
    float xcv = g_xc[bt0*DI + c];
    float zv  = g_xz[bt0*(2*DI) + DI + c];
    for (int t = 0; t < TT; t++) {
        float dtn = 0.0f, xcn = 0.0f, zn = 0.0f;
        if (t < TT-1) {
            size_t btn = bt0 + t + 1;
            dtn = g_dt[btn*DI + c];
            xcn = g_xc[btn*DI + c];
            zn  = g_xz[btn*(2*DI) + DI + c];
        }
        float dtxc = dtv * xcv;
        float y = 0.0f;
        if (structured) {
            float r = __expf(dtv * A0);
            float p = 1.0f;
            #pragma unroll
            for (int s = 0; s < DSN; s++) {
                p *= r;
                h[s] = p*h[s] + dtxc*sBC[t][s];
                y += h[s]*sBC[t][16+s];
            }
        } else {
            #pragma unroll
            for (int s = 0; s < DSN; s++) {
                float dA = __expf(dtv * Av[s]);
                h[s] = dA*h[s] + dtxc*sBC[t][s];
                y += h[s]*sBC[t][16+s];
            }
        }
        float yv = y + dpc*xcv;
        yv = yv * (zv / (1.0f + __expf(-zv)));
        g_y[(bt0 + t)*DI + c] = yv;
        dtv = dtn; xcv = xcn; zv = zn;
    }
}

// ---------------- residual + layernorm ----------------
__global__ void k_ln(const float* __restrict__ g, const float* __restrict__ bta) {
    __shared__ float red[4];
    int bt = blockIdx.x, d = threadIdx.x;
    float v = g_x2[(size_t)bt*DD + d] + g_out[(size_t)bt*DD + d];
    float s = v;
    #pragma unroll
    for (int o = 16; o > 0; o >>= 1) s += __shfl_xor_sync(0xffffffffu, s, o);
    if ((d & 31) == 0) red[d >> 5] = s;
    __syncthreads();
    float mean = (red[0] + red[1] + red[2] + red[3]) * (1.0f/DD);
    float dv = v - mean;
    float q = dv * dv;
    #pragma unroll
    for (int o = 16; o > 0; o >>= 1) q += __shfl_xor_sync(0xffffffffu, q, o);
    __syncthreads();
    if ((d & 31) == 0) red[d >> 5] = q;
    __syncthreads();
    float var = (red[0] + red[1] + red[2] + red[3]) * (1.0f/DD);
    g_x2[(size_t)bt*DD + d] = dv * rsqrtf(var + 1e-5f) * g[d] + bta[d];
}

// ---------------- xflat transpose into d_out ----------------
__global__ void k_xflat2(float* __restrict__ out) {
    __shared__ float sm[32][257];
    int b = blockIdx.x, d0 = blockIdx.y * 32;
    int tid = threadIdx.x;
    int tb = tid >> 5, dd = tid & 31;
    for (int t = tb; t < TT; t += 8)
        sm[dd][t] = g_x2[(size_t)(b*TT + t)*DD + d0 + dd];
    __syncthreads();
    for (int dd2 = 0; dd2 < 32; dd2++)
        out[(size_t)b*(DD*TT) + (d0+dd2)*TT + tid] = sm[dd2][tid];
}

// ---------------- pred head ----------------
__global__ void k_pred(const float* __restrict__ xflat, const float* __restrict__ fcw,
                       const float* __restrict__ fcb, float* __restrict__ pred) {
    __shared__ float red[8];
    int c = blockIdx.x, b = blockIdx.y, tid = threadIdx.x;
    const float4* x4 = (const float4*)(xflat + (size_t)b * (DD*TT));
    const float4* w4 = (const float4*)(fcw + (size_t)c * (DD*TT));
    float s = 0.0f;
    for (int i = tid; i < DD*TT/4; i += blockDim.x) {
        float4 a = x4[i], w = w4[i];
        s += a.x*w.x + a.y*w.y + a.z*w.z + a.w*w.w;
    }
    #pragma unroll
    for (int o = 16; o > 0; o >>= 1) s += __shfl_xor_sync(0xffffffffu, s, o);
    if ((tid & 31) == 0) red[tid >> 5] = s;
    __syncthreads();
    if (tid == 0) {
        float tot = 0.0f;
        for (int i = 0; i < (int)(blockDim.x >> 5); i++) tot += red[i];
        pred[b*CC + c] = tot + fcb[c];
    }
}

// ---------------- launch ----------------
extern "C" void kernel_launch(void* const* d_in, const int* in_sizes, int n_in,
                              void* d_out, int out_size) {
    const float* inputs    = (const float*)d_in[0];
    const float* emb_w     = (const float*)d_in[1];
    const float* emb_b     = (const float*)d_in[2];
    const float* blk_dw_w  = (const float*)d_in[3];
    const float* blk_dw_b  = (const float*)d_in[4];
    const float* blk_pw_w  = (const float*)d_in[5];
    const float* blk_pw_b  = (const float*)d_in[6];
    const float* blk_se_w1 = (const float*)d_in[7];
    const float* blk_se_b1 = (const float*)d_in[8];
    const float* blk_se_w2 = (const float*)d_in[9];
    const float* blk_se_b2 = (const float*)d_in[10];
    const float* mam_in_w  = (const float*)d_in[11];
    const float* mam_conv_w= (const float*)d_in[12];
    const float* mam_conv_b= (const float*)d_in[13];
    const float* mam_xproj = (const float*)d_in[14];
    const float* mam_dt_w  = (const float*)d_in[15];
    const float* mam_dt_b  = (const float*)d_in[16];
    const float* mam_Alog  = (const float*)d_in[17];
    const float* mam_D     = (const float*)d_in[18];
    const float* mam_out_w = (const float*)d_in[19];
    const float* ln_g      = (const float*)d_in[20];
    const float* ln_b      = (const float*)d_in[21];
    const float* fc_w      = (const float*)d_in[22];
    const float* fc_b      = (const float*)d_in[23];
    float* out = (float*)d_out;

    float *uA, *uB, *wA, *wB, *s2, *aa;
    cudaGetSymbolAddress((void**)&uA, g_uA);
    cudaGetSymbolAddress((void**)&uB, g_uB);
    cudaGetSymbolAddress((void**)&wA, g_wA);
    cudaGetSymbolAddress((void**)&wB, g_wB);
    cudaGetSymbolAddress((void**)&s2, g_s2);
    cudaGetSymbolAddress((void**)&aa, g_a);

    cudaFuncSetAttribute(k_block_mma,   cudaFuncAttributeMaxDynamicSharedMemorySize, SMEM_BLOCK);
    cudaFuncSetAttribute(k_gemm_nt_mma, cudaFuncAttributeMaxDynamicSharedMemorySize, SMEM_GEMM);

    k_emb<<<BMR, 256>>>(inputs, emb_w, emb_b);

    // block 0: read uA -> wA (no apply)
    k_block_mma<<<dim3(2, BMR), 256, SMEM_BLOCK>>>(uA, wA, aa, uB, wA, s2,
        blk_dw_w + 0*DD*KC, blk_dw_b + 0*DD, blk_pw_w + 0*DD*DD, blk_pw_b + 0*DD, 0);
    k_se2<<<BMR/8, 256>>>(blk_se_w1 + 0*DR*DD, blk_se_b1 + 0*DR, blk_se_w2 + 0*DD*DR, blk_se_b2 + 0*DD);
    // block 1: read uA,wA,a -> u1 into uB, w1 into wB
    k_block_mma<<<dim3(2, BMR), 256, SMEM_BLOCK>>>(uA, wA, aa, uB, wB, s2,
        blk_dw_w + 1*DD*KC, blk_dw_b + 1*DD, blk_pw_w + 1*DD*DD, blk_pw_b + 1*DD, 1);
    k_se2<<<BMR/8, 256>>>(blk_se_w1 + 1*DR*DD, blk_se_b1 + 1*DR, blk_se_w2 + 1*DD*DR, blk_se_b2 + 1*DD);
    // block 2: read uB,wB,a -> u2 into uA, w2 into wA
    k_block_mma<<<dim3(2, BMR), 256, SMEM_BLOCK>>>(uB, wB, aa, uA, wA, s2,
        blk_dw_w + 2*DD*KC, blk_dw_b + 2*DD, blk_pw_w + 2*DD*DD, blk_pw_b + 2*DD, 1);
    k_se2<<<BMR/8, 256>>>(blk_se_w1 + 2*DR*DD, blk_se_b1 + 2*DR, blk_se_w2 + 2*DD*DR, blk_se_b2 + 2*DD);

    k_smean2<<<dim3(NB, DD/32), 256>>>(uA, wA, aa);

    for (int i = 0; i < NMB; i++) {
        k_gemm_nt_mma<<<dim3(4, BT/128), 256, SMEM_GEMM>>>(0, mam_in_w + (size_t)i*2*DI*DD, DD);
        k_convsilu<<<(BT*DI)/256, 256>>>(mam_conv_w + i*DI*DCV, mam_conv_b + i*DI);
        k_dblt<<<BT/32, 256>>>(mam_xproj + (size_t)i*40*DI, mam_dt_w + i*DI*RKD, mam_dt_b + i*DI);
        k_scan<<<dim3(DI/128, NB), 128>>>(mam_Alog + i*DI*DSN, mam_D + i*DI);
        k_gemm_nt_mma<<<dim3(1, BT/128), 256, SMEM_GEMM>>>(1, mam_out_w + (size_t)i*DD*DI, DI);
        k_ln<<<BT, DD>>>(ln_g + i*DD, ln_b + i*DD);
    }

    k_xflat2<<<dim3(NB, DD/32), 256>>>(out);
    k_pred<<<dim3(CC, NB), 256>>>(out, fc_w, fc_b, out + (size_t)NB*DD*TT);
}

// round 16
// speedup vs baseline: 1.0858x; 1.0088x over previous
#include <cuda_runtime.h>
#include <math.h>
#include <stdint.h>

// ---------------- problem constants ----------------
#define NB   64
#define LL   2048
#define MS   12
#define DD   128
#define PP   16
#define SSTR 8
#define TT   256
#define KC   5
#define DR   32
#define NMB  2
#define DI   256
#define DCV  4
#define DSN  16
#define RKD  8
#define CC   18
#define BMR  768     // NB*MS
#define BT   16384   // NB*TT

#define PADK 68      // 64 + 4 pad (k-chunk tiles)
#define PADC 132     // 128 + 4 pad (C tile / staging rows)

// ---------------- scratch (device globals, no allocs) ----------------
__device__ float g_uA [BMR*DD*TT];
__device__ float g_uB [BMR*DD*TT];
__device__ float g_wA [BMR*DD*TT];
__device__ float g_wB [BMR*DD*TT];
__device__ float g_s2 [BMR*2*DD];
__device__ float g_a  [BMR*DD];
__device__ float g_x2 [BT*DD];
__device__ float g_xz [BT*2*DI];
__device__ float g_xc [BT*DI];
__device__ float g_dbl[BT*40];
__device__ float g_dt [BT*DI];
__device__ float g_y  [BT*DI];

// ---------------- helpers ----------------
__device__ __forceinline__ float rne_tf32(float x) {
    uint32_t u = __float_as_uint(x);
    u += 0xFFFu + ((u >> 13) & 1u);
    u &= 0xFFFFE000u;
    return __uint_as_float(u);
}

__device__ __forceinline__ void mma_tf32(float c[4],
    uint32_t a0, uint32_t a1, uint32_t a2, uint32_t a3,
    uint32_t b0, uint32_t b1)
{
    asm volatile(
        "mma.sync.aligned.m16n8k8.row.col.f32.tf32.tf32.f32 "
        "{%0,%1,%2,%3}, {%4,%5,%6,%7}, {%8,%9}, {%0,%1,%2,%3};"
        : "+f"(c[0]), "+f"(c[1]), "+f"(c[2]), "+f"(c[3])
        : "r"(a0), "r"(a1), "r"(a2), "r"(a3), "r"(b0), "r"(b1));
}

// dyn smem: sB[128][PADK] + sA[128][PADK] + su[64][PADC]
#define SMEM_BLOCK ((2*128*PADK + 64*PADC) * 4)   // 103424 B
#define SMEM_GEMM  (2 * 128 * PADK * 4)           // 69632 B

// ---------------- stage 1: embedding conv (register-held inputs) ----------------
__global__ void k_emb(const float* __restrict__ xin,
                      const float* __restrict__ w,
                      const float* __restrict__ bias) {
    __shared__ float srow[LL];
    __shared__ float sw[DD*PP];
    __shared__ float sb[DD];
    int bm = blockIdx.x;
    int b = bm / MS, m = bm % MS;
    const float* xp = xin + (size_t)b * (LL*MS) + m;
    for (int l = threadIdx.x; l < LL; l += blockDim.x) srow[l] = xp[(size_t)l * MS];
    for (int i = threadIdx.x; i < DD*PP; i += blockDim.x) sw[i] = w[i];
    for (int i = threadIdx.x; i < DD; i += blockDim.x) sb[i] = bias[i];
    __syncthreads();
    int t = threadIdx.x;
    int base = t * SSTR - 4;
    float x[PP];
    #pragma unroll
    for (int p = 0; p < PP; p++) {
        int l = base + p;
        x[p] = (l >= 0 && l < LL) ? srow[l] : 0.0f;
    }
    float* outp = g_uA + (size_t)bm * (DD*TT);
    for (int d = 0; d < DD; d++) {
        float acc = sb[d];
        #pragma unroll
        for (int p = 0; p < PP; p++) acc += sw[d*PP + p] * x[p];
        outp[d*TT + t] = acc;
    }
}

// ---------------- fused block kernel: float4 staging + tf32 mma (R10-proven) ----------------
// C[t][e] = sum_d V[t][d] * W[e][d];  V = gelu(dwconv(u [+ w_prev*a]))
__global__ void __launch_bounds__(256, 2) k_block_mma(
    const float* __restrict__ u_in, const float* __restrict__ w_prev,
    const float* __restrict__ a_prev, float* __restrict__ u_out,
    float* __restrict__ w_out, float* __restrict__ s_out,
    const float* __restrict__ dww, const float* __restrict__ dwb,
    const float* __restrict__ pwA, const float* __restrict__ pwb,
    int apply)
{
    extern __shared__ float dsm[];
    float* sB = dsm;                 // weights [e=128][64] pad PADK
    float* sA = dsm + 128*PADK;      // v       [t=128][64] pad PADK
    float* su = dsm + 2*128*PADK;    // u stage [64 d-rows][PADC]
    float* sC = dsm;                 // reuse sB+sA: [e=128][t] pad PADC
    __shared__ float sdw[DD*KC];
    __shared__ float sdb[DD];
    __shared__ float sa[DD];

    int bm = blockIdx.y, bn = blockIdx.x, t0 = bn * 128;
    int tid = threadIdx.x;
    int warp = tid >> 5, lane = tid & 31;
    int mbase = (warp & 3) * 32, nbase = (warp >> 2) * 64;
    int qr = lane >> 2, kb = lane & 3;

    for (int i = tid; i < DD*KC; i += 256) sdw[i] = dww[i];
    for (int i = tid; i < DD; i += 256) {
        sdb[i] = dwb[i];
        sa[i]  = apply ? a_prev[bm*DD + i] : 0.0f;
    }

    float acc[2][8][4];
    #pragma unroll
    for (int mt = 0; mt < 2; mt++)
        #pragma unroll
        for (int nt = 0; nt < 8; nt++) {
            acc[mt][nt][0]=0; acc[mt][nt][1]=0; acc[mt][nt][2]=0; acc[mt][nt][3]=0;
        }

    const float* up = u_in   + (size_t)bm * (DD*TT);
    const float* wp = w_prev + (size_t)bm * (DD*TT);
    float* uo = u_out + (size_t)bm * (DD*TT);

    for (int ch = 0; ch < 2; ch++) {
        int dbase = ch * 64;
        __syncthreads();   // params ready (ch0) / prior mma done reading tiles (ch1)
        // weights chunk -> sB[e][dd]
        for (int i = tid; i < 128*16; i += 256) {
            int e = i >> 4, c4 = (i & 15) << 2;
            float4 v = *(const float4*)&pwA[e*DD + dbase + c4];
            float* dst = &sB[e*PADK + c4];
            dst[0] = rne_tf32(v.x); dst[1] = rne_tf32(v.y);
            dst[2] = rne_tf32(v.z); dst[3] = rne_tf32(v.w);
        }
        // stage 64-d chunk of u_cur (float4 interior + scalar halo)
        if (apply) {
            #pragma unroll
            for (int q = 0; q < 8; q++) {
                int idx = q*256 + tid;
                int dr = idx >> 5, quad = idx & 31;
                int d = dbase + dr;
                int t = t0 + quad*4;
                float av = sa[d];
                float4 u4 = *(const float4*)&up[d*TT + t];
                float4 w4 = *(const float4*)&wp[d*TT + t];
                float4 v4;
                v4.x = u4.x + w4.x*av; v4.y = u4.y + w4.y*av;
                v4.z = u4.z + w4.z*av; v4.w = u4.w + w4.w*av;
                *(float4*)&uo[d*TT + t] = v4;
                float* s = &su[dr*PADC + 2 + quad*4];
                s[0]=v4.x; s[1]=v4.y; s[2]=v4.z; s[3]=v4.w;
            }
            {   // halo: j in {0,1,130,131}
                int dr = tid >> 2, h = tid & 3;
                int d = dbase + dr;
                int j = (h < 2) ? h : 128 + h;
                int t = t0 + j - 2;
                float val = 0.0f;
                if (t >= 0 && t < TT) val = up[d*TT + t] + wp[d*TT + t]*sa[d];
                su[dr*PADC + j] = val;
            }
        } else {
            #pragma unroll
            for (int q = 0; q < 8; q++) {
                int idx = q*256 + tid;
                int dr = idx >> 5, quad = idx & 31;
                int d = dbase + dr;
                int t = t0 + quad*4;
                float4 u4 = *(const float4*)&up[d*TT + t];
                float* s = &su[dr*PADC + 2 + quad*4];
                s[0]=u4.x; s[1]=u4.y; s[2]=u4.z; s[3]=u4.w;
            }
            {
                int dr = tid >> 2, h = tid & 3;
                int d = dbase + dr;
                int j = (h < 2) ? h : 128 + h;
                int t = t0 + j - 2;
                su[dr*PADC + j] = (t >= 0 && t < TT) ? up[d*TT + t] : 0.0f;
            }
        }
        __syncthreads();
        // conv + gelu from smem -> sA[t][dd]  (4 groups of 16 rows, no syncs)
        {
            int dr = tid >> 4, c0 = tid & 15;
            #pragma unroll
            for (int g = 0; g < 4; g++) {
                int drow = g*16 + dr;          // 0..63
                int d = dbase + drow;
                const float* sr = su + drow*PADC;
                float w0 = sdw[d*KC+0], w1 = sdw[d*KC+1], w2 = sdw[d*KC+2],
                      w3 = sdw[d*KC+3], w4 = sdw[d*KC+4];
                float bb = sdb[d];
                #pragma unroll
                for (int m = 0; m < 8; m++) {
                    int j = c0 + m*16;         // local t 0..127
                    float a = bb + w0*sr[j] + w1*sr[j+1] + w2*sr[j+2]
                                 + w3*sr[j+3] + w4*sr[j+4];
                    float v = 0.5f * a * (1.0f + erff(a * 0.7071067811865475f));
                    sA[j*PADK + drow] = rne_tf32(v);
                }
            }
        }
        __syncthreads();
        // mma over this chunk
        for (int ks = 0; ks < 8; ks++) {
            int k0 = ks * 8;
            uint32_t afr[2][4];
            #pragma unroll
            for (int mt = 0; mt < 2; mt++) {
                int row = mbase + mt*16 + qr;
                afr[mt][0] = __float_as_uint(sA[row*PADK     + k0 + kb]);
                afr[mt][1] = __float_as_uint(sA[(row+8)*PADK + k0 + kb]);
                afr[mt][2] = __float_as_uint(sA[row*PADK     + k0 + 4 + kb]);
                afr[mt][3] = __float_as_uint(sA[(row+8)*PADK + k0 + 4 + kb]);
            }
            #pragma unroll
            for (int nt = 0; nt < 8; nt++) {
                int nrow = nbase + nt*8 + qr;
                uint32_t b0 = __float_as_uint(sB[nrow*PADK + k0 + kb]);
                uint32_t b1 = __float_as_uint(sB[nrow*PADK + k0 + 4 + kb]);
                mma_tf32(acc[0][nt], afr[0][0], afr[0][1], afr[0][2], afr[0][3], b0, b1);
                mma_tf32(acc[1][nt], afr[1][0], afr[1][1], afr[1][2], afr[1][3], b0, b1);
            }
        }
    }
    __syncthreads();
    // frags -> sC[e][t]
    #pragma unroll
    for (int mt = 0; mt < 2; mt++) {
        int trow = mbase + mt*16 + qr;
        #pragma unroll
        for (int nt = 0; nt < 8; nt++) {
            int e0 = nbase + nt*8 + (lane & 3)*2;
            sC[e0*PADC + trow]         = acc[mt][nt][0];
            sC[(e0+1)*PADC + trow]     = acc[mt][nt][1];
            sC[e0*PADC + trow + 8]     = acc[mt][nt][2];
            sC[(e0+1)*PADC + trow + 8] = acc[mt][nt][3];
        }
    }
    __syncthreads();
    // epilogue: bias + store w_out[e][t] + t-sum
    {
        int e = tid >> 1, half = tid & 1;
        float bv = pwb[e];
        float ssum = 0.0f;
        float* worow = w_out + (size_t)bm * (DD*TT) + (size_t)e * TT + t0 + half*64;
        const float* src = sC + e*PADC + half*64;
        #pragma unroll
        for (int i = 0; i < 16; i++) {
            float4 o;
            o.x = src[4*i+0] + bv; o.y = src[4*i+1] + bv;
            o.z = src[4*i+2] + bv; o.w = src[4*i+3] + bv;
            ssum += o.x + o.y + o.z + o.w;
            *(float4*)(worow + 4*i) = o;
        }
        ssum += __shfl_xor_sync(0xffffffffu, ssum, 1);
        if (half == 0) s_out[(bm*2 + bn)*DD + e] = ssum;
    }
}

// ---------------- SE MLP v2: 8 bm per block, warp-parallel ----------------
__global__ void __launch_bounds__(256) k_se2(const float* __restrict__ w1, const float* __restrict__ b1,
                      const float* __restrict__ w2, const float* __restrict__ b2) {
    __shared__ float sw1[DR*129];
    __shared__ float sw2[DD*33];
    __shared__ float sb1[DR];
    __shared__ float sb2[DD];
    __shared__ float sss[8][DD];
    __shared__ float shh[8][DR];
    int tid = threadIdx.x;
    int warp = tid >> 5, lane = tid & 31;
    int bm0 = blockIdx.x * 8;

    for (int i = tid; i < DR*DD; i += 256) {
        int r = i >> 7, c = i & 127;
        sw1[r*129 + c] = w1[i];
    }
    for (int i = tid; i < DD*DR; i += 256) {
        int r = i >> 5, c = i & 31;
        sw2[r*33 + c] = w2[i];
    }
    for (int i = tid; i < DR; i += 256) sb1[i] = b1[i];
    for (int i = tid; i < DD; i += 256) sb2[i] = b2[i];
    {
        int bm = bm0 + warp;
        #pragma unroll
        for (int q = 0; q < 4; q++) {
            int d = lane + q*32;
            sss[warp][d] = (g_s2[(bm*2+0)*DD + d] + g_s2[(bm*2+1)*DD + d]) * (1.0f/TT);
        }
    }
    __syncthreads();
    {
        float acc = sb1[lane];
        const float* ssp = sss[warp];
        #pragma unroll 8
        for (int d = 0; d < DD; d++) acc += sw1[lane*129 + d] * ssp[d];
        shh[warp][lane] = fmaxf(acc, 0.0f);
    }
    __syncwarp();
    {
        int bm = bm0 + warp;
        const float* hp = shh[warp];
        #pragma unroll
        for (int q = 0; q < 4; q++) {
            int d = lane + q*32;
            float acc = sb2[d];
            #pragma unroll
            for (int j = 0; j < DR; j++) acc += sw2[d*33 + j] * hp[j];
            g_a[bm*DD + d] = 1.0f / (1.0f + __expf(-acc));
        }
    }
}

// ---------------- final apply + sensor mean + transpose (float4 loads) ----------------
__global__ void k_smean2(const float* __restrict__ u, const float* __restrict__ w,
                         const float* __restrict__ a) {
    __shared__ float sm[32][257];
    int b = blockIdx.x, d0 = blockIdx.y * 32;
    int tid = threadIdx.x;
    int tq = tid & 63;            // t quad: t = tq*4
    int dg = tid >> 6;            // 0..3
    #pragma unroll
    for (int dd = 0; dd < 8; dd++) {
        int drow = dg*8 + dd;
        int d = d0 + drow;
        float sx = 0.0f, sy = 0.0f, sz = 0.0f, sw_ = 0.0f;
        #pragma unroll
        for (int m = 0; m < MS; m++) {
            int bm = b*MS + m;
            size_t o = (size_t)bm*(DD*TT) + (size_t)d*TT + tq*4;
            float4 u4 = *(const float4*)&u[o];
            float4 w4 = *(const float4*)&w[o];
            float av = a[bm*DD + d];
            sx += u4.x + w4.x*av; sy += u4.y + w4.y*av;
            sz += u4.z + w4.z*av; sw_ += u4.w + w4.w*av;
        }
        float* dst = &sm[drow][tq*4];
        dst[0] = sx*(1.0f/MS); dst[1] = sy*(1.0f/MS);
        dst[2] = sz*(1.0f/MS); dst[3] = sw_*(1.0f/MS);
    }
    __syncthreads();
    int t2 = tid >> 5, dd2 = tid & 31;
    for (int tt = t2; tt < TT; tt += 8)
        g_x2[(size_t)(b*TT + tt)*DD + d0 + dd2] = sm[dd2][tt];
}

// ---------------- NT GEMM via tf32 mma; mode1 fuses residual+LayerNorm ----------------
__global__ void __launch_bounds__(256, 2) k_gemm_nt_mma(int mode, const float* __restrict__ Bw, int K,
                                                        const float* __restrict__ lng,
                                                        const float* __restrict__ lnb) {
    extern __shared__ float dsm[];
    float* sA = dsm;
    float* sB = dsm + 128*PADK;
    float* sC = dsm;
    const float* A; int lda;
    if (mode == 0) { A = g_x2; lda = DD; }
    else           { A = g_y;  lda = DI; }
    int bm0 = blockIdx.y * 128, bn0 = blockIdx.x * 128;
    int tid = threadIdx.x;
    int warp = tid >> 5, lane = tid & 31;
    int mbase = (warp & 3) * 32, nbase = (warp >> 2) * 64;
    int qr = lane >> 2, kb = lane & 3;

    float acc[2][8][4];
    #pragma unroll
    for (int mt = 0; mt < 2; mt++)
        #pragma unroll
        for (int nt = 0; nt < 8; nt++) {
            acc[mt][nt][0]=0; acc[mt][nt][1]=0; acc[mt][nt][2]=0; acc[mt][nt][3]=0;
        }

    for (int kc = 0; kc < K; kc += 64) {
        __syncthreads();
        for (int i = tid; i < 128*16; i += 256) {
            int r = i >> 4, c4 = (i & 15) << 2;
            float4 v = *(const float4*)&A[(size_t)(bm0 + r)*lda + kc + c4];
            float* dst = &sA[r*PADK + c4];
            dst[0] = rne_tf32(v.x); dst[1] = rne_tf32(v.y);
            dst[2] = rne_tf32(v.z); dst[3] = rne_tf32(v.w);
        }
        for (int i = tid; i < 128*16; i += 256) {
            int r = i >> 4, c4 = (i & 15) << 2;
            float4 v = *(const float4*)&Bw[(size_t)(bn0 + r)*K + kc + c4];
            float* dst = &sB[r*PADK + c4];
            dst[0] = rne_tf32(v.x); dst[1] = rne_tf32(v.y);
            dst[2] = rne_tf32(v.z); dst[3] = rne_tf32(v.w);
        }
        __syncthreads();
        for (int ks = 0; ks < 8; ks++) {
            int k0 = ks * 8;
            uint32_t afr[2][4];
            #pragma unroll
            for (int mt = 0; mt < 2; mt++) {
                int row = mbase + mt*16 + qr;
                afr[mt][0] = __float_as_uint(sA[row*PADK     + k0 + kb]);
                afr[mt][1] = __float_as_uint(sA[(row+8)*PADK + k0 + kb]);
                afr[mt][2] = __float_as_uint(sA[row*PADK     + k0 + 4 + kb]);
                afr[mt][3] = __float_as_uint(sA[(row+8)*PADK + k0 + 4 + kb]);
            }
            #pragma unroll
            for (int nt = 0; nt < 8; nt++) {
                int nrow = nbase + nt*8 + qr;
                uint32_t b0 = __float_as_uint(sB[nrow*PADK + k0 + kb]);
                uint32_t b1 = __float_as_uint(sB[nrow*PADK + k0 + 4 + kb]);
                mma_tf32(acc[0][nt], afr[0][0], afr[0][1], afr[0][2], afr[0][3], b0, b1);
                mma_tf32(acc[1][nt], afr[1][0], afr[1][1], afr[1][2], afr[1][3], b0, b1);
            }
        }
    }
    __syncthreads();
    #pragma unroll
    for (int mt = 0; mt < 2; mt++) {
        int mrow = mbase + mt*16 + qr;
        #pragma unroll
        for (int nt = 0; nt < 8; nt++) {
            int n0 = nbase + nt*8 + (lane & 3)*2;
            *(float2*)&sC[mrow*PADC + n0]     = make_float2(acc[mt][nt][0], acc[mt][nt][1]);
            *(float2*)&sC[(mrow+8)*PADC + n0] = make_float2(acc[mt][nt][2], acc[mt][nt][3]);
        }
    }
    __syncthreads();
    if (mode == 0) {
        int m = tid >> 1, half = tid & 1;
        float* crow = g_xz + (size_t)(bm0 + m)*(2*DI) + bn0 + half*64;
        const float* src = sC + m*PADC + half*64;
        #pragma unroll
        for (int i = 0; i < 16; i++)
            *(float4*)(crow + 4*i) = *(const float4*)(src + 4*i);
    } else {
        // residual + layernorm, write g_x2 in place
        int m = tid >> 1, half = tid & 1;
        float* x2row = g_x2 + (size_t)(bm0 + m)*DD + half*64;
        float* srcm = sC + m*PADC + half*64;
        float s1 = 0.0f, s2 = 0.0f;
        #pragma unroll
        for (int i = 0; i < 16; i++) {
            float4 c = *(float4*)&srcm[4*i];
            float4 r = *(const float4*)&x2row[4*i];
            float4 v;
            v.x = c.x + r.x; v.y = c.y + r.y; v.z = c.z + r.z; v.w = c.w + r.w;
            s1 += v.x + v.y + v.z + v.w;
            s2 += v.x*v.x + v.y*v.y + v.z*v.z + v.w*v.w;
            *(float4*)&srcm[4*i] = v;
        }
        s1 += __shfl_xor_sync(0xffffffffu, s1, 1);
        s2 += __shfl_xor_sync(0xffffffffu, s2, 1);
        float mean = s1 * (1.0f/DD);
        float var  = s2 * (1.0f/DD) - mean*mean;
        float scl  = rsqrtf(var + 1e-5f);
        #pragma unroll
        for (int i = 0; i < 16; i++) {
            float4 v  = *(float4*)&srcm[4*i];
            float4 gg = *(const float4*)&lng[half*64 + 4*i];
            float4 bb = *(const float4*)&lnb[half*64 + 4*i];
            float4 o;
            o.x = (v.x - mean)*scl*gg.x + bb.x;
            o.y = (v.y - mean)*scl*gg.y + bb.y;
            o.z = (v.z - mean)*scl*gg.z + bb.z;
            o.w = (v.w - mean)*scl*gg.w + bb.w;
            *(float4*)&x2row[4*i] = o;
        }
    }
}

// ---------------- mamba: causal depthwise conv + silu ----------------
__global__ void k_convsilu(const float* __restrict__ cw, const float* __restrict__ cb) {
    int idx = blockIdx.x * blockDim.x + threadIdx.x;
    if (idx >= BT*DI) return;
    int c = idx & (DI-1);
    int t = (idx >> 8) & (TT-1);
    int b = idx >> 16;
    float acc = cb[c];
    #pragma unroll
    for (int j = 0; j < DCV; j++) {
        int tt = t - 3 + j;
        if (tt >= 0) acc += cw[c*DCV + j] * g_xz[(size_t)(b*TT + tt)*(2*DI) + c];
    }
    g_xc[idx] = acc / (1.0f + __expf(-acc));
}

// ---------------- mamba: dbl = xc @ xproj^T, fused dt ----------------
__global__ void k_dblt(const float* __restrict__ xp,
                       const float* __restrict__ dtw, const float* __restrict__ dtb) {
    __shared__ float sx[32][DI+1];
    __shared__ float sd[32][RKD];
    int t0 = blockIdx.x * 32;
    int tid = threadIdx.x;
    for (int i = tid; i < 32*DI; i += 256) {
        int tt = i >> 8, c = i & (DI-1);
        sx[tt][c] = g_xc[(size_t)(t0 + tt)*DI + c];
    }
    __syncthreads();
    for (int o = tid; o < 32*40; o += 256) {
        int tt = o & 31, k = o >> 5;
        const float* wrow = xp + k*DI;
        float acc = 0.0f;
        #pragma unroll 8
        for (int c = 0; c < DI; c++) acc += wrow[c] * sx[tt][c];
        if (k < RKD) sd[tt][k] = acc;
        else g_dbl[(size_t)(t0 + tt)*40 + k] = acc;
    }
    __syncthreads();
    {
        int c = tid;
        float wreg[RKD];
        #pragma unroll
        for (int r = 0; r < RKD; r++) wreg[r] = dtw[c*RKD + r];
        float bb = dtb[c];
        for (int tt = 0; tt < 32; tt++) {
            float acc = bb;
            #pragma unroll
            for (int r = 0; r < RKD; r++) acc += wreg[r] * sd[tt][r];
            g_dt[(size_t)(t0 + tt)*DI + c] = (acc > 20.0f) ? acc : log1pf(__expf(acc));
        }
    }
}

// ---------------- mamba: selective scan + gate (prefetched) ----------------
__global__ void k_scan(const float* __restrict__ Alog, const float* __restrict__ Dp) {
    __shared__ float sBC[TT][32];
    int b = blockIdx.y;
    int c = blockIdx.x * blockDim.x + threadIdx.x;
    for (int i = threadIdx.x; i < TT*32; i += blockDim.x) {
        int tt = i >> 5, j = i & 31;
        sBC[tt][j] = g_dbl[(size_t)(b*TT + tt)*40 + 8 + j];
    }
    __syncthreads();
    float Av[DSN];
    #pragma unroll
    for (int s = 0; s < DSN; s++) Av[s] = -__expf(Alog[c*DSN + s]);
    float A0 = Av[0];
    bool structured = true;
    #pragma unroll
    for (int s = 0; s < DSN; s++)
        if (fabsf(Av[s] - (float)(s+1)*A0) > 1e-4f * fabsf(Av[s])) structured = false;
    float h[DSN];
    #pragma unroll
    for (int s = 0; s < DSN; s++) h[s] = 0.0f;
    float dpc = Dp[c];
    size_t bt0 = (size_t)(b*TT);
    float dtv = g_dt[bt0*DI + c];
    float xcv = g_xc[bt0*DI + c];
    float zv  = g_xz[bt0*(2*DI) + DI + c];
    for (int t = 0; t < TT; t++) {
        float dtn = 0.0f, xcn = 0.0f, zn = 0.0f;
        if (t < TT-1) {
            size_t btn = bt0 + t + 1;
            dtn = g_dt[btn*DI + c];
            xcn = g_xc[btn*DI + c];
            zn  = g_xz[btn*(2*DI) + DI + c];
        }
        float dtxc = dtv * xcv;
        float y = 0.0f;
        if (structured) {
            float r = __expf(dtv * A0);
            float p = 1.0f;
            #pragma unroll
            for (int s = 0; s < DSN; s++) {
                p *= r;
                h[s] = p*h[s] + dtxc*sBC[t][s];
                y += h[s]*sBC[t][16+s];
            }
        } else {
            #pragma unroll
            for (int s = 0; s < DSN; s++) {
                float dA = __expf(dtv * Av[s]);
                h[s] = dA*h[s] + dtxc*sBC[t][s];
                y += h[s]*sBC[t][16+s];
            }
        }
        float yv = y + dpc*xcv;
        yv = yv * (zv / (1.0f + __expf(-zv)));
        g_y[(bt0 + t)*DI + c] = yv;
        dtv = dtn; xcv = xcn; zv = zn;
    }
}

// ---------------- xflat transpose into d_out ----------------
__global__ void k_xflat2(float* __restrict__ out) {
    __shared__ float sm[32][257];
    int b = blockIdx.x, d0 = blockIdx.y * 32;
    int tid = threadIdx.x;
    int tb = tid >> 5, dd = tid & 31;
    for (int t = tb; t < TT; t += 8)
        sm[dd][t] = g_x2[(size_t)(b*TT + t)*DD + d0 + dd];
    __syncthreads();
    for (int dd2 = 0; dd2 < 32; dd2++)
        out[(size_t)b*(DD*TT) + (d0+dd2)*TT + tid] = sm[dd2][tid];
}

// ---------------- pred head ----------------
__global__ void k_pred(const float* __restrict__ xflat, const float* __restrict__ fcw,
                       const float* __restrict__ fcb, float* __restrict__ pred) {
    __shared__ float red[8];
    int c = blockIdx.x, b = blockIdx.y, tid = threadIdx.x;
    const float4* x4 = (const float4*)(xflat + (size_t)b * (DD*TT));
    const float4* w4 = (const float4*)(fcw + (size_t)c * (DD*TT));
    float s = 0.0f;
    for (int i = tid; i < DD*TT/4; i += blockDim.x) {
        float4 a = x4[i], w = w4[i];
        s += a.x*w.x + a.y*w.y + a.z*w.z + a.w*w.w;
    }
    #pragma unroll
    for (int o = 16; o > 0; o >>= 1) s += __shfl_xor_sync(0xffffffffu, s, o);
    if ((tid & 31) == 0) red[tid >> 5] = s;
    __syncthreads();
    if (tid == 0) {
        float tot = 0.0f;
        for (int i = 0; i < (int)(blockDim.x >> 5); i++) tot += red[i];
        pred[b*CC + c] = tot + fcb[c];
    }
}

// ---------------- launch ----------------
extern "C" void kernel_launch(void* const* d_in, const int* in_sizes, int n_in,
                              void* d_out, int out_size) {
    const float* inputs    = (const float*)d_in[0];
    const float* emb_w     = (const float*)d_in[1];
    const float* emb_b     = (const float*)d_in[2];
    const float* blk_dw_w  = (const float*)d_in[3];
    const float* blk_dw_b  = (const float*)d_in[4];
    const float* blk_pw_w  = (const float*)d_in[5];
    const float* blk_pw_b  = (const float*)d_in[6];
    const float* blk_se_w1 = (const float*)d_in[7];
    const float* blk_se_b1 = (const float*)d_in[8];
    const float* blk_se_w2 = (const float*)d_in[9];
    const float* blk_se_b2 = (const float*)d_in[10];
    const float* mam_in_w  = (const float*)d_in[11];
    const float* mam_conv_w= (const float*)d_in[12];
    const float* mam_conv_b= (const float*)d_in[13];
    const float* mam_xproj = (const float*)d_in[14];
    const float* mam_dt_w  = (const float*)d_in[15];
    const float* mam_dt_b  = (const float*)d_in[16];
    const float* mam_Alog  = (const float*)d_in[17];
    const float* mam_D     = (const float*)d_in[18];
    const float* mam_out_w = (const float*)d_in[19];
    const float* ln_g      = (const float*)d_in[20];
    const float* ln_b      = (const float*)d_in[21];
    const float* fc_w      = (const float*)d_in[22];
    const float* fc_b      = (const float*)d_in[23];
    float* out = (float*)d_out;

    float *uA, *uB, *wA, *wB, *s2, *aa;
    cudaGetSymbolAddress((void**)&uA, g_uA);
    cudaGetSymbolAddress((void**)&uB, g_uB);
    cudaGetSymbolAddress((void**)&wA, g_wA);
    cudaGetSymbolAddress((void**)&wB, g_wB);
    cudaGetSymbolAddress((void**)&s2, g_s2);
    cudaGetSymbolAddress((void**)&aa, g_a);

    cudaFuncSetAttribute(k_block_mma,   cudaFuncAttributeMaxDynamicSharedMemorySize, SMEM_BLOCK);
    cudaFuncSetAttribute(k_gemm_nt_mma, cudaFuncAttributeMaxDynamicSharedMemorySize, SMEM_GEMM);

    k_emb<<<BMR, 256>>>(inputs, emb_w, emb_b);

    // block 0: read uA -> wA (no apply)
    k_block_mma<<<dim3(2, BMR), 256, SMEM_BLOCK>>>(uA, wA, aa, uB, wA, s2,
        blk_dw_w + 0*DD*KC, blk_dw_b + 0*DD, blk_pw_w + 0*DD*DD, blk_pw_b + 0*DD, 0);
    k_se2<<<BMR/8, 256>>>(blk_se_w1 + 0*DR*DD, blk_se_b1 + 0*DR, blk_se_w2 + 0*DD*DR, blk_se_b2 + 0*DD);
    // block 1: read uA,wA,a -> u1 into uB, w1 into wB
    k_block_mma<<<dim3(2, BMR), 256, SMEM_BLOCK>>>(uA, wA, aa, uB, wB, s2,
        blk_dw_w + 1*DD*KC, blk_dw_b + 1*DD, blk_pw_w + 1*DD*DD, blk_pw_b + 1*DD, 1);
    k_se2<<<BMR/8, 256>>>(blk_se_w1 + 1*DR*DD, blk_se_b1 + 1*DR, blk_se_w2 + 1*DD*DR, blk_se_b2 + 1*DD);
    // block 2: read uB,wB,a -> u2 into uA, w2 into wA
    k_block_mma<<<dim3(2, BMR), 256, SMEM_BLOCK>>>(uB, wB, aa, uA, wA, s2,
        blk_dw_w + 2*DD*KC, blk_dw_b + 2*DD, blk_pw_w + 2*DD*DD, blk_pw_b + 2*DD, 1);
    k_se2<<<BMR/8, 256>>>(blk_se_w1 + 2*DR*DD, blk_se_b1 + 2*DR, blk_se_w2 + 2*DD*DR, blk_se_b2 + 2*DD);

    k_smean2<<<dim3(NB, DD/32), 256>>>(uA, wA, aa);

    for (int i = 0; i < NMB; i++) {
        k_gemm_nt_mma<<<dim3(4, BT/128), 256, SMEM_GEMM>>>(0, mam_in_w + (size_t)i*2*DI*DD, DD,
                                                           (const float*)0, (const float*)0);
        k_convsilu<<<(BT*DI)/256, 256>>>(mam_conv_w + i*DI*DCV, mam_conv_b + i*DI);
        k_dblt<<<BT/32, 256>>>(mam_xproj + (size_t)i*40*DI, mam_dt_w + i*DI*RKD, mam_dt_b + i*DI);
        k_scan<<<dim3(DI/128, NB), 128>>>(mam_Alog + i*DI*DSN, mam_D + i*DI);
        k_gemm_nt_mma<<<dim3(1, BT/128), 256, SMEM_GEMM>>>(1, mam_out_w + (size_t)i*DD*DI, DI,
                                                           ln_g + i*DD, ln_b + i*DD);
    }

    k_xflat2<<<dim3(NB, DD/32), 256>>>(out);
    k_pred<<<dim3(CC, NB), 256>>>(out, fc_w, fc_b, out + (size_t)NB*DD*TT);
}

// round 17
// speedup vs baseline: 1.1112x; 1.0234x over previous
#include <cuda_runtime.h>
#include <math.h>
#include <stdint.h>

// ---------------- problem constants ----------------
#define NB   64
#define LL   2048
#define MS   12
#define DD   128
#define PP   16
#define SSTR 8
#define TT   256
#define KC   5
#define DR   32
#define NMB  2
#define DI   256
#define DCV  4
#define DSN  16
#define RKD  8
#define CC   18
#define BMR  768     // NB*MS
#define BT   16384   // NB*TT

#define PADK 68      // 64 + 4 pad (k-chunk tiles)
#define PADC 132     // 128 + 4 pad (C tile / staging rows)
#define SXZ_S 257    // cdblt row stride (conflict-free)

// ---------------- scratch (device globals, no allocs) ----------------
__device__ float g_uA [BMR*DD*TT];
__device__ float g_uB [BMR*DD*TT];
__device__ float g_wA [BMR*DD*TT];
__device__ float g_wB [BMR*DD*TT];
__device__ float g_s2 [BMR*2*DD];
__device__ float g_a  [BMR*DD];
__device__ float g_x2 [BT*DD];
__device__ float g_xz [BT*2*DI];
__device__ float g_xc [BT*DI];
__device__ float g_dbl[BT*40];
__device__ float g_dt [BT*DI];
__device__ float g_y  [BT*DI];

// ---------------- helpers ----------------
__device__ __forceinline__ float rne_tf32(float x) {
    uint32_t u = __float_as_uint(x);
    u += 0xFFFu + ((u >> 13) & 1u);
    u &= 0xFFFFE000u;
    return __uint_as_float(u);
}

__device__ __forceinline__ void mma_tf32(float c[4],
    uint32_t a0, uint32_t a1, uint32_t a2, uint32_t a3,
    uint32_t b0, uint32_t b1)
{
    asm volatile(
        "mma.sync.aligned.m16n8k8.row.col.f32.tf32.tf32.f32 "
        "{%0,%1,%2,%3}, {%4,%5,%6,%7}, {%8,%9}, {%0,%1,%2,%3};"
        : "+f"(c[0]), "+f"(c[1]), "+f"(c[2]), "+f"(c[3])
        : "r"(a0), "r"(a1), "r"(a2), "r"(a3), "r"(b0), "r"(b1));
}

// dyn smem: sB[128][PADK] + sA[128][PADK] + su[64][PADC]
#define SMEM_BLOCK ((2*128*PADK + 64*PADC) * 4)   // 103424 B
#define SMEM_GEMM  (2 * 128 * PADK * 4)           // 69632 B

// ---------------- stage 1: embedding conv (register-held inputs) ----------------
__global__ void k_emb(const float* __restrict__ xin,
                      const float* __restrict__ w,
                      const float* __restrict__ bias) {
    __shared__ float srow[LL];
    __shared__ float sw[DD*PP];
    __shared__ float sb[DD];
    int bm = blockIdx.x;
    int b = bm / MS, m = bm % MS;
    const float* xp = xin + (size_t)b * (LL*MS) + m;
    for (int l = threadIdx.x; l < LL; l += blockDim.x) srow[l] = xp[(size_t)l * MS];
    for (int i = threadIdx.x; i < DD*PP; i += blockDim.x) sw[i] = w[i];
    for (int i = threadIdx.x; i < DD; i += blockDim.x) sb[i] = bias[i];
    __syncthreads();
    int t = threadIdx.x;
    int base = t * SSTR - 4;
    float x[PP];
    #pragma unroll
    for (int p = 0; p < PP; p++) {
        int l = base + p;
        x[p] = (l >= 0 && l < LL) ? srow[l] : 0.0f;
    }
    float* outp = g_uA + (size_t)bm * (DD*TT);
    for (int d = 0; d < DD; d++) {
        float acc = sb[d];
        #pragma unroll
        for (int p = 0; p < PP; p++) acc += sw[d*PP + p] * x[p];
        outp[d*TT + t] = acc;
    }
}

// ---------------- fused block kernel: float4 staging + tf32 mma (R10-proven) ----------------
// C[t][e] = sum_d V[t][d] * W[e][d];  V = gelu(dwconv(u [+ w_prev*a]))
__global__ void __launch_bounds__(256, 2) k_block_mma(
    const float* __restrict__ u_in, const float* __restrict__ w_prev,
    const float* __restrict__ a_prev, float* __restrict__ u_out,
    float* __restrict__ w_out, float* __restrict__ s_out,
    const float* __restrict__ dww, const float* __restrict__ dwb,
    const float* __restrict__ pwA, const float* __restrict__ pwb,
    int apply)
{
    extern __shared__ float dsm[];
    float* sB = dsm;                 // weights [e=128][64] pad PADK
    float* sA = dsm + 128*PADK;      // v       [t=128][64] pad PADK
    float* su = dsm + 2*128*PADK;    // u stage [64 d-rows][PADC]
    float* sC = dsm;                 // reuse sB+sA: [e=128][t] pad PADC
    __shared__ float sdw[DD*KC];
    __shared__ float sdb[DD];
    __shared__ float sa[DD];

    int bm = blockIdx.y, bn = blockIdx.x, t0 = bn * 128;
    int tid = threadIdx.x;
    int warp = tid >> 5, lane = tid & 31;
    int mbase = (warp & 3) * 32, nbase = (warp >> 2) * 64;
    int qr = lane >> 2, kb = lane & 3;

    for (int i = tid; i < DD*KC; i += 256) sdw[i] = dww[i];
    for (int i = tid; i < DD; i += 256) {
        sdb[i] = dwb[i];
        sa[i]  = apply ? a_prev[bm*DD + i] : 0.0f;
    }

    float acc[2][8][4];
    #pragma unroll
    for (int mt = 0; mt < 2; mt++)
        #pragma unroll
        for (int nt = 0; nt < 8; nt++) {
            acc[mt][nt][0]=0; acc[mt][nt][1]=0; acc[mt][nt][2]=0; acc[mt][nt][3]=0;
        }

    const float* up = u_in   + (size_t)bm * (DD*TT);
    const float* wp = w_prev + (size_t)bm * (DD*TT);
    float* uo = u_out + (size_t)bm * (DD*TT);

    for (int ch = 0; ch < 2; ch++) {
        int dbase = ch * 64;
        __syncthreads();   // params ready (ch0) / prior mma done reading tiles (ch1)
        // weights chunk -> sB[e][dd]
        for (int i = tid; i < 128*16; i += 256) {
            int e = i >> 4, c4 = (i & 15) << 2;
            float4 v = *(const float4*)&pwA[e*DD + dbase + c4];
            float* dst = &sB[e*PADK + c4];
            dst[0] = rne_tf32(v.x); dst[1] = rne_tf32(v.y);
            dst[2] = rne_tf32(v.z); dst[3] = rne_tf32(v.w);
        }
        // stage 64-d chunk of u_cur (float4 interior + scalar halo)
        if (apply) {
            #pragma unroll
            for (int q = 0; q < 8; q++) {
                int idx = q*256 + tid;
                int dr = idx >> 5, quad = idx & 31;
                int d = dbase + dr;
                int t = t0 + quad*4;
                float av = sa[d];
                float4 u4 = *(const float4*)&up[d*TT + t];
                float4 w4 = *(const float4*)&wp[d*TT + t];
                float4 v4;
                v4.x = u4.x + w4.x*av; v4.y = u4.y + w4.y*av;
                v4.z = u4.z + w4.z*av; v4.w = u4.w + w4.w*av;
                *(float4*)&uo[d*TT + t] = v4;
                float* s = &su[dr*PADC + 2 + quad*4];
                s[0]=v4.x; s[1]=v4.y; s[2]=v4.z; s[3]=v4.w;
            }
            {   // halo: j in {0,1,130,131}
                int dr = tid >> 2, h = tid & 3;
                int d = dbase + dr;
                int j = (h < 2) ? h : 128 + h;
                int t = t0 + j - 2;
                float val = 0.0f;
                if (t >= 0 && t < TT) val = up[d*TT + t] + wp[d*TT + t]*sa[d];
                su[dr*PADC + j] = val;
            }
        } else {
            #pragma unroll
            for (int q = 0; q < 8; q++) {
                int idx = q*256 + tid;
                int dr = idx >> 5, quad = idx & 31;
                int d = dbase + dr;
                int t = t0 + quad*4;
                float4 u4 = *(const float4*)&up[d*TT + t];
                float* s = &su[dr*PADC + 2 + quad*4];
                s[0]=u4.x; s[1]=u4.y; s[2]=u4.z; s[3]=u4.w;
            }
            {
                int dr = tid >> 2, h = tid & 3;
                int d = dbase + dr;
                int j = (h < 2) ? h : 128 + h;
                int t = t0 + j - 2;
                su[dr*PADC + j] = (t >= 0 && t < TT) ? up[d*TT + t] : 0.0f;
            }
        }
        __syncthreads();
        // conv + gelu from smem -> sA[t][dd]  (4 groups of 16 rows, no syncs)
        {
            int dr = tid >> 4, c0 = tid & 15;
            #pragma unroll
            for (int g = 0; g < 4; g++) {
                int drow = g*16 + dr;          // 0..63
                int d = dbase + drow;
                const float* sr = su + drow*PADC;
                float w0 = sdw[d*KC+0], w1 = sdw[d*KC+1], w2 = sdw[d*KC+2],
                      w3 = sdw[d*KC+3], w4 = sdw[d*KC+4];
                float bb = sdb[d];
                #pragma unroll
                for (int m = 0; m < 8; m++) {
                    int j = c0 + m*16;         // local t 0..127
                    float a = bb + w0*sr[j] + w1*sr[j+1] + w2*sr[j+2]
                                 + w3*sr[j+3] + w4*sr[j+4];
                    float v = 0.5f * a * (1.0f + erff(a * 0.7071067811865475f));
                    sA[j*PADK + drow] = rne_tf32(v);
                }
            }
        }
        __syncthreads();
        // mma over this chunk
        for (int ks = 0; ks < 8; ks++) {
            int k0 = ks * 8;
            uint32_t afr[2][4];
            #pragma unroll
            for (int mt = 0; mt < 2; mt++) {
                int row = mbase + mt*16 + qr;
                afr[mt][0] = __float_as_uint(sA[row*PADK     + k0 + kb]);
                afr[mt][1] = __float_as_uint(sA[(row+8)*PADK + k0 + kb]);
                afr[mt][2] = __float_as_uint(sA[row*PADK     + k0 + 4 + kb]);
                afr[mt][3] = __float_as_uint(sA[(row+8)*PADK + k0 + 4 + kb]);
            }
            #pragma unroll
            for (int nt = 0; nt < 8; nt++) {
                int nrow = nbase + nt*8 + qr;
                uint32_t b0 = __float_as_uint(sB[nrow*PADK + k0 + kb]);
                uint32_t b1 = __float_as_uint(sB[nrow*PADK + k0 + 4 + kb]);
                mma_tf32(acc[0][nt], afr[0][0], afr[0][1], afr[0][2], afr[0][3], b0, b1);
                mma_tf32(acc[1][nt], afr[1][0], afr[1][1], afr[1][2], afr[1][3], b0, b1);
            }
        }
    }
    __syncthreads();
    // frags -> sC[e][t]
    #pragma unroll
    for (int mt = 0; mt < 2; mt++) {
        int trow = mbase + mt*16 + qr;
        #pragma unroll
        for (int nt = 0; nt < 8; nt++) {
            int e0 = nbase + nt*8 + (lane & 3)*2;
            sC[e0*PADC + trow]         = acc[mt][nt][0];
            sC[(e0+1)*PADC + trow]     = acc[mt][nt][1];
            sC[e0*PADC + trow + 8]     = acc[mt][nt][2];
            sC[(e0+1)*PADC + trow + 8] = acc[mt][nt][3];
        }
    }
    __syncthreads();
    // epilogue: bias + store w_out[e][t] + t-sum
    {
        int e = tid >> 1, half = tid & 1;
        float bv = pwb[e];
        float ssum = 0.0f;
        float* worow = w_out + (size_t)bm * (DD*TT) + (size_t)e * TT + t0 + half*64;
        const float* src = sC + e*PADC + half*64;
        #pragma unroll
        for (int i = 0; i < 16; i++) {
            float4 o;
            o.x = src[4*i+0] + bv; o.y = src[4*i+1] + bv;
            o.z = src[4*i+2] + bv; o.w = src[4*i+3] + bv;
            ssum += o.x + o.y + o.z + o.w;
            *(float4*)(worow + 4*i) = o;
        }
        ssum += __shfl_xor_sync(0xffffffffu, ssum, 1);
        if (half == 0) s_out[(bm*2 + bn)*DD + e] = ssum;
    }
}

// ---------------- SE MLP v2: 8 bm per block, warp-parallel ----------------
__global__ void __launch_bounds__(256) k_se2(const float* __restrict__ w1, const float* __restrict__ b1,
                      const float* __restrict__ w2, const float* __restrict__ b2) {
    __shared__ float sw1[DR*129];
    __shared__ float sw2[DD*33];
    __shared__ float sb1[DR];
    __shared__ float sb2[DD];
    __shared__ float sss[8][DD];
    __shared__ float shh[8][DR];
    int tid = threadIdx.x;
    int warp = tid >> 5, lane = tid & 31;
    int bm0 = blockIdx.x * 8;

    for (int i = tid; i < DR*DD; i += 256) {
        int r = i >> 7, c = i & 127;
        sw1[r*129 + c] = w1[i];
    }
    for (int i = tid; i < DD*DR; i += 256) {
        int r = i >> 5, c = i & 31;
        sw2[r*33 + c] = w2[i];
    }
    for (int i = tid; i < DR; i += 256) sb1[i] = b1[i];
    for (int i = tid; i < DD; i += 256) sb2[i] = b2[i];
    {
        int bm = bm0 + warp;
        #pragma unroll
        for (int q = 0; q < 4; q++) {
            int d = lane + q*32;
            sss[warp][d] = (g_s2[(bm*2+0)*DD + d] + g_s2[(bm*2+1)*DD + d]) * (1.0f/TT);
        }
    }
    __syncthreads();
    {
        float acc = sb1[lane];
        const float* ssp = sss[warp];
        #pragma unroll 8
        for (int d = 0; d < DD; d++) acc += sw1[lane*129 + d] * ssp[d];
        shh[warp][lane] = fmaxf(acc, 0.0f);
    }
    __syncwarp();
    {
        int bm = bm0 + warp;
        const float* hp = shh[warp];
        #pragma unroll
        for (int q = 0; q < 4; q++) {
            int d = lane + q*32;
            float acc = sb2[d];
            #pragma unroll
            for (int j = 0; j < DR; j++) acc += sw2[d*33 + j] * hp[j];
            g_a[bm*DD + d] = 1.0f / (1.0f + __expf(-acc));
        }
    }
}

// ---------------- final apply + sensor mean + transpose (float4 loads) ----------------
__global__ void k_smean2(const float* __restrict__ u, const float* __restrict__ w,
                         const float* __restrict__ a) {
    __shared__ float sm[32][257];
    int b = blockIdx.x, d0 = blockIdx.y * 32;
    int tid = threadIdx.x;
    int tq = tid & 63;            // t quad: t = tq*4
    int dg = tid >> 6;            // 0..3
    #pragma unroll
    for (int dd = 0; dd < 8; dd++) {
        int drow = dg*8 + dd;
        int d = d0 + drow;
        float sx = 0.0f, sy = 0.0f, sz = 0.0f, sw_ = 0.0f;
        #pragma unroll
        for (int m = 0; m < MS; m++) {
            int bm = b*MS + m;
            size_t o = (size_t)bm*(DD*TT) + (size_t)d*TT + tq*4;
            float4 u4 = *(const float4*)&u[o];
            float4 w4 = *(const float4*)&w[o];
            float av = a[bm*DD + d];
            sx += u4.x + w4.x*av; sy += u4.y + w4.y*av;
            sz += u4.z + w4.z*av; sw_ += u4.w + w4.w*av;
        }
        float* dst = &sm[drow][tq*4];
        dst[0] = sx*(1.0f/MS); dst[1] = sy*(1.0f/MS);
        dst[2] = sz*(1.0f/MS); dst[3] = sw_*(1.0f/MS);
    }
    __syncthreads();
    int t2 = tid >> 5, dd2 = tid & 31;
    for (int tt = t2; tt < TT; tt += 8)
        g_x2[(size_t)(b*TT + tt)*DD + d0 + dd2] = sm[dd2][tt];
}

// ---------------- NT GEMM via tf32 mma; mode1 fuses residual+LayerNorm ----------------
__global__ void __launch_bounds__(256, 2) k_gemm_nt_mma(int mode, const float* __restrict__ Bw, int K,
                                                        const float* __restrict__ lng,
                                                        const float* __restrict__ lnb) {
    extern __shared__ float dsm[];
    float* sA = dsm;
    float* sB = dsm + 128*PADK;
    float* sC = dsm;
    const float* A; int lda;
    if (mode == 0) { A = g_x2; lda = DD; }
    else           { A = g_y;  lda = DI; }
    int bm0 = blockIdx.y * 128, bn0 = blockIdx.x * 128;
    int tid = threadIdx.x;
    int warp = tid >> 5, lane = tid & 31;
    int mbase = (warp & 3) * 32, nbase = (warp >> 2) * 64;
    int qr = lane >> 2, kb = lane & 3;

    float acc[2][8][4];
    #pragma unroll
    for (int mt = 0; mt < 2; mt++)
        #pragma unroll
        for (int nt = 0; nt < 8; nt++) {
            acc[mt][nt][0]=0; acc[mt][nt][1]=0; acc[mt][nt][2]=0; acc[mt][nt][3]=0;
        }

    for (int kc = 0; kc < K; kc += 64) {
        __syncthreads();
        for (int i = tid; i < 128*16; i += 256) {
            int r = i >> 4, c4 = (i & 15) << 2;
            float4 v = *(const float4*)&A[(size_t)(bm0 + r)*lda + kc + c4];
            float* dst = &sA[r*PADK + c4];
            dst[0] = rne_tf32(v.x); dst[1] = rne_tf32(v.y);
            dst[2] = rne_tf32(v.z); dst[3] = rne_tf32(v.w);
        }
        for (int i = tid; i < 128*16; i += 256) {
            int r = i >> 4, c4 = (i & 15) << 2;
            float4 v = *(const float4*)&Bw[(size_t)(bn0 + r)*K + kc + c4];
            float* dst = &sB[r*PADK + c4];
            dst[0] = rne_tf32(v.x); dst[1] = rne_tf32(v.y);
            dst[2] = rne_tf32(v.z); dst[3] = rne_tf32(v.w);
        }
        __syncthreads();
        for (int ks = 0; ks < 8; ks++) {
            int k0 = ks * 8;
            uint32_t afr[2][4];
            #pragma unroll
            for (int mt = 0; mt < 2; mt++) {
                int row = mbase + mt*16 + qr;
                afr[mt][0] = __float_as_uint(sA[row*PADK     + k0 + kb]);
                afr[mt][1] = __float_as_uint(sA[(row+8)*PADK + k0 + kb]);
                afr[mt][2] = __float_as_uint(sA[row*PADK     + k0 + 4 + kb]);
                afr[mt][3] = __float_as_uint(sA[(row+8)*PADK + k0 + 4 + kb]);
            }
            #pragma unroll
            for (int nt = 0; nt < 8; nt++) {
                int nrow = nbase + nt*8 + qr;
                uint32_t b0 = __float_as_uint(sB[nrow*PADK + k0 + kb]);
                uint32_t b1 = __float_as_uint(sB[nrow*PADK + k0 + 4 + kb]);
                mma_tf32(acc[0][nt], afr[0][0], afr[0][1], afr[0][2], afr[0][3], b0, b1);
                mma_tf32(acc[1][nt], afr[1][0], afr[1][1], afr[1][2], afr[1][3], b0, b1);
            }
        }
    }
    __syncthreads();
    #pragma unroll
    for (int mt = 0; mt < 2; mt++) {
        int mrow = mbase + mt*16 + qr;
        #pragma unroll
        for (int nt = 0; nt < 8; nt++) {
            int n0 = nbase + nt*8 + (lane & 3)*2;
            *(float2*)&sC[mrow*PADC + n0]     = make_float2(acc[mt][nt][0], acc[mt][nt][1]);
            *(float2*)&sC[(mrow+8)*PADC + n0] = make_float2(acc[mt][nt][2], acc[mt][nt][3]);
        }
    }
    __syncthreads();
    if (mode == 0) {
        int m = tid >> 1, half = tid & 1;
        float* crow = g_xz + (size_t)(bm0 + m)*(2*DI) + bn0 + half*64;
        const float* src = sC + m*PADC + half*64;
        #pragma unroll
        for (int i = 0; i < 16; i++)
            *(float4*)(crow + 4*i) = *(const float4*)(src + 4*i);
    } else {
        // residual + layernorm, write g_x2 in place
        int m = tid >> 1, half = tid & 1;
        float* x2row = g_x2 + (size_t)(bm0 + m)*DD + half*64;
        float* srcm = sC + m*PADC + half*64;
        float s1 = 0.0f, s2 = 0.0f;
        #pragma unroll
        for (int i = 0; i < 16; i++) {
            float4 c = *(float4*)&srcm[4*i];
            float4 r = *(const float4*)&x2row[4*i];
            float4 v;
            v.x = c.x + r.x; v.y = c.y + r.y; v.z = c.z + r.z; v.w = c.w + r.w;
            s1 += v.x + v.y + v.z + v.w;
            s2 += v.x*v.x + v.y*v.y + v.z*v.z + v.w*v.w;
            *(float4*)&srcm[4*i] = v;
        }
        s1 += __shfl_xor_sync(0xffffffffu, s1, 1);
        s2 += __shfl_xor_sync(0xffffffffu, s2, 1);
        float mean = s1 * (1.0f/DD);
        float var  = s2 * (1.0f/DD) - mean*mean;
        float scl  = rsqrtf(var + 1e-5f);
        #pragma unroll
        for (int i = 0; i < 16; i++) {
            float4 v  = *(float4*)&srcm[4*i];
            float4 gg = *(const float4*)&lng[half*64 + 4*i];
            float4 bb = *(const float4*)&lnb[half*64 + 4*i];
            float4 o;
            o.x = (v.x - mean)*scl*gg.x + bb.x;
            o.y = (v.y - mean)*scl*gg.y + bb.y;
            o.z = (v.z - mean)*scl*gg.z + bb.z;
            o.w = (v.w - mean)*scl*gg.w + bb.w;
            *(float4*)&x2row[4*i] = o;
        }
    }
}

// ---------------- mamba: fused conv+silu + dbl + dt (slim, in-place sx) ----------------
__global__ void __launch_bounds__(256) k_cdblt(const float* __restrict__ xp,
                       const float* __restrict__ cw, const float* __restrict__ cb,
                       const float* __restrict__ dtw, const float* __restrict__ dtb) {
    __shared__ float sxz[35*SXZ_S];   // rows 0..34: xi halo+tile; rows 3..34 become xc
    __shared__ float sd[32*RKD];
    int bt0 = blockIdx.x * 32;
    int tl0 = bt0 & (TT-1);
    int tid = threadIdx.x;
    // load xi rows (t-3..t+31) cols 0..255
    for (int i = tid; i < 35*256; i += 256) {
        int r = i >> 8, c = i & 255;
        int rt = r - 3;
        float v = 0.0f;
        if (tl0 + rt >= 0) v = g_xz[(size_t)(bt0 + rt)*(2*DI) + c];
        sxz[r*SXZ_S + c] = v;
    }
    __syncthreads();
    // conv + silu, write xc over row tt+3 (read exactly once before overwrite)
    {
        int c = tid;
        float w0=cw[c*DCV+0], w1=cw[c*DCV+1], w2=cw[c*DCV+2], w3=cw[c*DCV+3];
        float bb = cb[c];
        float x0 = sxz[0*SXZ_S+c], x1 = sxz[1*SXZ_S+c], x2 = sxz[2*SXZ_S+c];
        #pragma unroll 4
        for (int tt = 0; tt < 32; tt++) {
            float x3 = sxz[(tt+3)*SXZ_S + c];
            float a = bb + w0*x0 + w1*x1 + w2*x2 + w3*x3;
            float v = a / (1.0f + __expf(-a));
            g_xc[(size_t)(bt0+tt)*DI + c] = v;
            sxz[(tt+3)*SXZ_S + c] = v;
            x0 = x1; x1 = x2; x2 = x3;
        }
    }
    __syncthreads();
    // dbl: rows 3..34 of sxz hold xc[tt=0..31]
    for (int o = tid; o < 32*40; o += 256) {
        int tt = o & 31, k = o >> 5;
        const float* wrow = xp + k*DI;
        const float* sx = &sxz[(tt+3)*SXZ_S];
        float acc = 0.0f;
        #pragma unroll 8
        for (int c = 0; c < DI; c++) acc += wrow[c] * sx[c];
        if (k < RKD) sd[tt*RKD + k] = acc;
        else g_dbl[(size_t)(bt0 + tt)*40 + k] = acc;
    }
    __syncthreads();
    // dt
    {
        int c = tid;
        float wreg[RKD];
        #pragma unroll
        for (int r = 0; r < RKD; r++) wreg[r] = dtw[c*RKD + r];
        float bb = dtb[c];
        for (int tt = 0; tt < 32; tt++) {
            float acc = bb;
            #pragma unroll
            for (int r = 0; r < RKD; r++) acc += wreg[r] * sd[tt*RKD + r];
            g_dt[(size_t)(bt0 + tt)*DI + c] = (acc > 20.0f) ? acc : log1pf(__expf(acc));
        }
    }
}

// ---------------- mamba: selective scan + gate (prefetched) ----------------
__global__ void k_scan(const float* __restrict__ Alog, const float* __restrict__ Dp) {
    __shared__ float sBC[TT][32];
    int b = blockIdx.y;
    int c = blockIdx.x * blockDim.x + threadIdx.x;
    for (int i = threadIdx.x; i < TT*32; i += blockDim.x) {
        int tt = i >> 5, j = i & 31;
        sBC[tt][j] = g_dbl[(size_t)(b*TT + tt)*40 + 8 + j];
    }
    __syncthreads();
    float Av[DSN];
    #pragma unroll
    for (int s = 0; s < DSN; s++) Av[s] = -__expf(Alog[c*DSN + s]);
    float A0 = Av[0];
    bool structured = true;
    #pragma unroll
    for (int s = 0; s < DSN; s++)
        if (fabsf(Av[s] - (float)(s+1)*A0) > 1e-4f * fabsf(Av[s])) structured = false;
    float h[DSN];
    #pragma unroll
    for (int s = 0; s < DSN; s++) h[s] = 0.0f;
    float dpc = Dp[c];
    size_t bt0 = (size_t)(b*TT);
    float dtv = g_dt[bt0*DI + c];
    float xcv = g_xc[bt0*DI + c];
    float zv  = g_xz[bt0*(2*DI) + DI + c];
    for (int t = 0; t < TT; t++) {
        float dtn = 0.0f, xcn = 0.0f, zn = 0.0f;
        if (t < TT-1) {
            size_t btn = bt0 + t + 1;
            dtn = g_dt[btn*DI + c];
            xcn = g_xc[btn*DI + c];
            zn  = g_xz[btn*(2*DI) + DI + c];
        }
        float dtxc = dtv * xcv;
        float y = 0.0f;
        if (structured) {
            float r = __expf(dtv * A0);
            float p = 1.0f;
            #pragma unroll
            for (int s = 0; s < DSN; s++) {
                p *= r;
                h[s] = p*h[s] + dtxc*sBC[t][s];
                y += h[s]*sBC[t][16+s];
            }
        } else {
            #pragma unroll
            for (int s = 0; s < DSN; s++) {
                float dA = __expf(dtv * Av[s]);
                h[s] = dA*h[s] + dtxc*sBC[t][s];
                y += h[s]*sBC[t][16+s];
            }
        }
        float yv = y + dpc*xcv;
        yv = yv * (zv / (1.0f + __expf(-zv)));
        g_y[(bt0 + t)*DI + c] = yv;
        dtv = dtn; xcv = xcn; zv = zn;
    }
}

// ---------------- xflat transpose into d_out ----------------
__global__ void k_xflat2(float* __restrict__ out) {
    __shared__ float sm[32][257];
    int b = blockIdx.x, d0 = blockIdx.y * 32;
    int tid = threadIdx.x;
    int tb = tid >> 5, dd = tid & 31;
    for (int t = tb; t < TT; t += 8)
        sm[dd][t] = g_x2[(size_t)(b*TT + t)*DD + d0 + dd];
    __syncthreads();
    for (int dd2 = 0; dd2 < 32; dd2++)
        out[(size_t)b*(DD*TT) + (d0+dd2)*TT + tid] = sm[dd2][tid];
}

// ---------------- pred head ----------------
__global__ void k_pred(const float* __restrict__ xflat, const float* __restrict__ fcw,
                       const float* __restrict__ fcb, float* __restrict__ pred) {
    __shared__ float red[8];
    int c = blockIdx.x, b = blockIdx.y, tid = threadIdx.x;
    const float4* x4 = (const float4*)(xflat + (size_t)b * (DD*TT));
    const float4* w4 = (const float4*)(fcw + (size_t)c * (DD*TT));
    float s = 0.0f;
    for (int i = tid; i < DD*TT/4; i += blockDim.x) {
        float4 a = x4[i], w = w4[i];
        s += a.x*w.x + a.y*w.y + a.z*w.z + a.w*w.w;
    }
    #pragma unroll
    for (int o = 16; o > 0; o >>= 1) s += __shfl_xor_sync(0xffffffffu, s, o);
    if ((tid & 31) == 0) red[tid >> 5] = s;
    __syncthreads();
    if (tid == 0) {
        float tot = 0.0f;
        for (int i = 0; i < (int)(blockDim.x >> 5); i++) tot += red[i];
        pred[b*CC + c] = tot + fcb[c];
    }
}

// ---------------- launch ----------------
extern "C" void kernel_launch(void* const* d_in, const int* in_sizes, int n_in,
                              void* d_out, int out_size) {
    const float* inputs    = (const float*)d_in[0];
    const float* emb_w     = (const float*)d_in[1];
    const float* emb_b     = (const float*)d_in[2];
    const float* blk_dw_w  = (const float*)d_in[3];
    const float* blk_dw_b  = (const float*)d_in[4];
    const float* blk_pw_w  = (const float*)d_in[5];
    const float* blk_pw_b  = (const float*)d_in[6];
    const float* blk_se_w1 = (const float*)d_in[7];
    const float* blk_se_b1 = (const float*)d_in[8];
    const float* blk_se_w2 = (const float*)d_in[9];
    const float* blk_se_b2 = (const float*)d_in[10];
    const float* mam_in_w  = (const float*)d_in[11];
    const float* mam_conv_w= (const float*)d_in[12];
    const float* mam_conv_b= (const float*)d_in[13];
    const float* mam_xproj = (const float*)d_in[14];
    const float* mam_dt_w  = (const float*)d_in[15];
    const float* mam_dt_b  = (const float*)d_in[16];
    const float* mam_Alog  = (const float*)d_in[17];
    const float* mam_D     = (const float*)d_in[18];
    const float* mam_out_w = (const float*)d_in[19];
    const float* ln_g      = (const float*)d_in[20];
    const float* ln_b      = (const float*)d_in[21];
    const float* fc_w      = (const float*)d_in[22];
    const float* fc_b      = (const float*)d_in[23];
    float* out = (float*)d_out;

    float *uA, *uB, *wA, *wB, *s2, *aa;
    cudaGetSymbolAddress((void**)&uA, g_uA);
    cudaGetSymbolAddress((void**)&uB, g_uB);
    cudaGetSymbolAddress((void**)&wA, g_wA);
    cudaGetSymbolAddress((void**)&wB, g_wB);
    cudaGetSymbolAddress((void**)&s2, g_s2);
    cudaGetSymbolAddress((void**)&aa, g_a);

    cudaFuncSetAttribute(k_block_mma,   cudaFuncAttributeMaxDynamicSharedMemorySize, SMEM_BLOCK);
    cudaFuncSetAttribute(k_gemm_nt_mma, cudaFuncAttributeMaxDynamicSharedMemorySize, SMEM_GEMM);

    k_emb<<<BMR, 256>>>(inputs, emb_w, emb_b);

    // block 0: read uA -> wA (no apply)
    k_block_mma<<<dim3(2, BMR), 256, SMEM_BLOCK>>>(uA, wA, aa, uB, wA, s2,
        blk_dw_w + 0*DD*KC, blk_dw_b + 0*DD, blk_pw_w + 0*DD*DD, blk_pw_b + 0*DD, 0);
    k_se2<<<BMR/8, 256>>>(blk_se_w1 + 0*DR*DD, blk_se_b1 + 0*DR, blk_se_w2 + 0*DD*DR, blk_se_b2 + 0*DD);
    // block 1: read uA,wA,a -> u1 into uB, w1 into wB
    k_block_mma<<<dim3(2, BMR), 256, SMEM_BLOCK>>>(uA, wA, aa, uB, wB, s2,
        blk_dw_w + 1*DD*KC, blk_dw_b + 1*DD, blk_pw_w + 1*DD*DD, blk_pw_b + 1*DD, 1);
    k_se2<<<BMR/8, 256>>>(blk_se_w1 + 1*DR*DD, blk_se_b1 + 1*DR, blk_se_w2 + 1*DD*DR, blk_se_b2 + 1*DD);
    // block 2: read uB,wB,a -> u2 into uA, w2 into wA
    k_block_mma<<<dim3(2, BMR), 256, SMEM_BLOCK>>>(uB, wB, aa, uA, wA, s2,
        blk_dw_w + 2*DD*KC, blk_dw_b + 2*DD, blk_pw_w + 2*DD*DD, blk_pw_b + 2*DD, 1);
    k_se2<<<BMR/8, 256>>>(blk_se_w1 + 2*DR*DD, blk_se_b1 + 2*DR, blk_se_w2 + 2*DD*DR, blk_se_b2 + 2*DD);

    k_smean2<<<dim3(NB, DD/32), 256>>>(uA, wA, aa);

    for (int i = 0; i < NMB; i++) {
        k_gemm_nt_mma<<<dim3(4, BT/128), 256, SMEM_GEMM>>>(0, mam_in_w + (size_t)i*2*DI*DD, DD,
                                                           (const float*)0, (const float*)0);
        k_cdblt<<<BT/32, 256>>>(mam_xproj + (size_t)i*40*DI,
                                mam_conv_w + i*DI*DCV, mam_conv_b + i*DI,
                                mam_dt_w + i*DI*RKD, mam_dt_b + i*DI);
        k_scan<<<dim3(DI/128, NB), 128>>>(mam_Alog + i*DI*DSN, mam_D + i*DI);
        k_gemm_nt_mma<<<dim3(1, BT/128), 256, SMEM_GEMM>>>(1, mam_out_w + (size_t)i*DD*DI, DI,
                                                           ln_g + i*DD, ln_b + i*DD);
    }

    k_xflat2<<<dim3(NB, DD/32), 256>>>(out);
    k_pred<<<dim3(CC, NB), 256>>>(out, fc_w, fc_b, out + (size_t)NB*DD*TT);
}